// round 14
// baseline (speedup 1.0000x reference)
#include <cuda_runtime.h>
#include <cuda_bf16.h>
#include <cstdint>

#define NCOLS 24576   // B*3*N = 4*3*2048
#define NPTS  2048
#define BATCH 4
#define KNN   20

// ---------------- static scratch (bf16 hi/lo activations, [col][channel]) ----------------
__device__ __nv_bfloat16 g_XIN0h[6291456], g_XIN0l[6291456];   // [24576][256]
__device__ __nv_bfloat16 g_Yh[6291456],   g_Yl[6291456];       // [24576][256]
__device__ __nv_bfloat16 g_Hh[3145728],   g_Hl[3145728];       // [24576][128]
__device__ __nv_bfloat16 g_Y2h[3145728],  g_Y2l[3145728];
__device__ __nv_bfloat16 g_N0h[3145728],  g_N0l[3145728];
__device__ __nv_bfloat16 g_N1h[3145728],  g_N1l[3145728];
__device__ __nv_bfloat16 g_Wh[819200],    g_Wl[819200];
__device__ float g_mean[BATCH * NPTS * 3];
__device__ float g_pool[256 * 12];
__device__ float g_ppart[16 * 128 * 12];
__device__ float g_Pd0[256 * 12];
__device__ float g_PWs[128 * 12];

// weight regions inside g_Wh/g_Wl
#define OFF_D0  0         // 5 x 256x256
#define OFF_W0  327680    // 5 x 128x256
#define OFF_D1  491520    // 5 x 128x128
#define OFF_SW0 573440    // block0 [Ws|W1] 128x384
#define OFF_SWI 622592    // blocks1-4 [Ws[:, :128]|W1] 128x256 each

// ---------------- ptx helpers ----------------
__device__ __forceinline__ void cpa16(uint32_t dst, const void* src) {
    asm volatile("cp.async.cg.shared.global [%0], [%1], 16;\n" :: "r"(dst), "l"(src));
}
__device__ __forceinline__ void ldsm4(uint32_t* r, uint32_t addr) {
    asm volatile("ldmatrix.sync.aligned.m8n8.x4.shared.b16 {%0,%1,%2,%3}, [%4];"
                 : "=r"(r[0]), "=r"(r[1]), "=r"(r[2]), "=r"(r[3]) : "r"(addr));
}
__device__ __forceinline__ void mma16816(float* c, const uint32_t* a, const uint32_t* b) {
    asm volatile("mma.sync.aligned.m16n8k16.row.col.f32.bf16.bf16.f32 "
                 "{%0,%1,%2,%3}, {%4,%5,%6,%7}, {%8,%9}, {%0,%1,%2,%3};"
                 : "+f"(c[0]), "+f"(c[1]), "+f"(c[2]), "+f"(c[3])
                 : "r"(a[0]), "r"(a[1]), "r"(a[2]), "r"(a[3]), "r"(b[0]), "r"(b[1]));
}
__device__ __forceinline__ float bfre(__nv_bfloat16 h, __nv_bfloat16 l) {
    return __bfloat162float(h) + __bfloat162float(l);
}

// SW128 swizzle: bits[6:4] ^= bits[9:7] (conflict-free ldsm on 128B rows)
#define SWZ128(x) ((x) ^ (((x) >> 3) & 0x70))

// stage: A[128 rows][128B: hi 64 | lo 64] 16384B, then B[96 rows][128B] 12288B
#define FSTG 28672u
#define BOFS 16384u

// ---------------- all weight splits in ONE launch ----------------
__global__ __launch_bounds__(256) void splitall(const float* __restrict__ d0,
                                                const float* __restrict__ W0,
                                                const float* __restrict__ d1,
                                                const float* __restrict__ W1,
                                                const float* __restrict__ Ws,
                                                __nv_bfloat16* __restrict__ Wh,
                                                __nv_bfloat16* __restrict__ Wl) {
    int i = blockIdx.x * 256 + threadIdx.x;
    float x; int di;
    if (i < 327680) { x = d0[i]; di = OFF_D0 + i; }
    else if (i < 491520) { int j = i - 327680; x = W0[j]; di = OFF_W0 + j; }
    else if (i < 573440) { int j = i - 491520; x = d1[j]; di = OFF_D1 + j; }
    else if (i < 622592) {
        int j = i - 573440; int m = j / 384, k = j - m * 384;
        x = (k < 256) ? Ws[m*256 + k] : W1[m*128 + (k - 256)];
        di = OFF_SW0 + j;
    } else if (i < 753664) {
        int j = i - 622592; int blk = j >> 15; int jj = j & 32767;
        int m = jj >> 8, k = jj & 255;
        x = (k < 128) ? Ws[(blk+1)*32768 + m*256 + k] : W1[(blk+1)*16384 + m*128 + (k-128)];
        di = OFF_SWI + j;
    } else return;
    __nv_bfloat16 h = __float2bfloat16(x);
    Wh[di] = h;
    Wl[di] = __float2bfloat16(x - __bfloat162float(h));
}

// ---------------- KNN mean: 4 queries per block, 2 warps per query ----------------
__global__ __launch_bounds__(256) void knn_mean4(const float* __restrict__ p,
                                                 float* __restrict__ outm) {
    extern __shared__ float sm[];
    float* sx = sm;              // 2048
    float* sy = sm + 2048;
    float* sz = sm + 4096;
    float* sd = sm + 6144;       // 4 x 2048
    __shared__ float swv[4][2];
    __shared__ int   swi[4][2];
    __shared__ float sacc[4][3];
    int blk = blockIdx.x;        // 0..2047
    int b = blk >> 9;            // 512 blocks per batch
    int q0 = (blk & 511) * 4;    // base query index within batch
    int tid = threadIdx.x;
    const float* pb = p + b * NPTS * 3;
    for (int i = tid; i < NPTS; i += 256) {
        sx[i] = pb[i*3+0]; sy[i] = pb[i*3+1]; sz[i] = pb[i*3+2];
    }
    if (tid < 4) { sacc[tid][0] = 0.f; sacc[tid][1] = 0.f; sacc[tid][2] = 0.f; }
    __syncthreads();
    float qx[4], qy[4], qz[4], qq[4];
#pragma unroll
    for (int qi = 0; qi < 4; qi++) {
        int n = q0 + qi;
        qx[qi] = sx[n]; qy[qi] = sy[n]; qz[qi] = sz[n];
        qq[qi] = qx[qi]*qx[qi] + qy[qi]*qy[qi] + qz[qi]*qz[qi];
    }
    for (int i = tid; i < NPTS; i += 256) {
        float x = sx[i], y = sy[i], z = sz[i];
        float xx = x*x + y*y + z*z;
#pragma unroll
        for (int qi = 0; qi < 4; qi++)
            sd[qi*2048 + i] = 2.f*(qx[qi]*x + qy[qi]*y + qz[qi]*z) - qq[qi] - xx;
    }
    __syncthreads();
    int w = tid >> 5, lane = tid & 31;
    int myq = w >> 1, half = w & 1;
    float* sdq = sd + myq * 2048;
    for (int r = 0; r < KNN; r++) {
        float bv = -3.4e38f; int bi = 1 << 30;
#pragma unroll 4
        for (int j = 0; j < 32; j++) {
            int i = half*1024 + j*32 + lane;
            float v = sdq[i];
            if (v > bv) { bv = v; bi = i; }        // ascending i -> smallest idx wins ties
        }
        for (int off = 16; off; off >>= 1) {
            float ov = __shfl_down_sync(0xffffffffu, bv, off);
            int   oi = __shfl_down_sync(0xffffffffu, bi, off);
            if (ov > bv || (ov == bv && oi < bi)) { bv = ov; bi = oi; }
        }
        if (lane == 0) { swv[myq][half] = bv; swi[myq][half] = bi; }
        __syncthreads();
        if (lane == 0 && half == 0) {
            float v0 = swv[myq][0], v1 = swv[myq][1];
            int   i0 = swi[myq][0], i1 = swi[myq][1];
            int bj = (v0 > v1 || (v0 == v1 && i0 < i1)) ? i0 : i1;
            sacc[myq][0] += sx[bj];
            sacc[myq][1] += sy[bj];
            sacc[myq][2] += sz[bj];
            sdq[bj] = -3.4e38f;
        }
        __syncthreads();
    }
    if (tid < 4) {
        int gid = b * NPTS + q0 + tid;
        const float inv = 1.f / KNN;
        outm[gid*3+0] = sacc[tid][0] * inv;
        outm[gid*3+1] = sacc[tid][1] * inv;
        outm[gid*3+2] = sacc[tid][2] * inv;
    }
}

// ------------- feat: out[col][256] bf16 hi/lo -------------
__global__ __launch_bounds__(256) void feat_t(const float* __restrict__ p,
                                              const float* __restrict__ m,
                                              const float* __restrict__ W,
                                              __nv_bfloat16* __restrict__ Xh,
                                              __nv_bfloat16* __restrict__ Xl) {
    __shared__ float sW[768];
    int tid = threadIdx.x;
    for (int i = tid; i < 768; i += 256) sW[i] = W[i];
    __syncthreads();
    int wid = tid >> 5, lane = tid & 31;
    int col = blockIdx.x * 8 + wid;
    int b = col / 6144;
    int rem = col - b * 6144;
    int v = rem >> 11;
    int n = rem & 2047;
    int pi = (b * NPTS + n) * 3;
    float px = p[pi], py = p[pi+1], pz = p[pi+2];
    float mx = m[pi], my = m[pi+1], mz = m[pi+2];
    float pv, mv, cv;
    if (v == 0)      { pv = px; mv = mx; cv = my*pz - mz*py; }
    else if (v == 1) { pv = py; mv = my; cv = mz*px - mx*pz; }
    else             { pv = pz; mv = mz; cv = mx*py - my*px; }
#pragma unroll
    for (int j = 0; j < 8; j++) {
        int o = j * 32 + lane;
        float r = sW[o*3]*(mv - pv) + sW[o*3+1]*pv + sW[o*3+2]*cv;
        size_t idx = (size_t)col * 256 + o;
        __nv_bfloat16 h = __float2bfloat16(r);
        Xh[idx] = h;
        Xl[idx] = __float2bfloat16(r - __bfloat162float(h));
    }
}

// ---------------- plain split-bf16 HMMA GEMM, templated K (full unroll) ----------------
// BM=128, BN=96, BK=32; 384 threads = 12 warps (4m x 3n), warp tile 32x32; 3-stage pipeline.
template<int K, int KSPLIT>
__global__ __launch_bounds__(384, 2)
void hgemm(const __nv_bfloat16* __restrict__ Ah, const __nv_bfloat16* __restrict__ Al,
           int lda,
           const __nv_bfloat16* __restrict__ B1h, const __nv_bfloat16* __restrict__ B1l, int ldb1,
           const __nv_bfloat16* __restrict__ B2h, const __nv_bfloat16* __restrict__ B2l, int ldb2,
           __nv_bfloat16* __restrict__ Ch, __nv_bfloat16* __restrict__ Cl, int ldc,
           const float* __restrict__ bias)
{
    extern __shared__ __align__(16) unsigned char dsm[];
    uint32_t smB = (uint32_t)__cvta_generic_to_shared(dsm);
    int tid = threadIdx.x, lane = tid & 31, wid = tid >> 5;
    int wm = wid & 3, wn = wid >> 2;
    int col0 = blockIdx.x * 96, m0 = blockIdx.y * 128;

    float acc[2][4][4];
#pragma unroll
    for (int a = 0; a < 2; a++)
#pragma unroll
        for (int b = 0; b < 4; b++)
#pragma unroll
            for (int c = 0; c < 4; c++) acc[a][b][c] = 0.f;

    constexpr int S = K >> 5;

    auto load_stage = [&](int s, int kc) {
        uint32_t SB = smB + (uint32_t)s * FSTG;
        int kk = kc << 5;
#pragma unroll
        for (int part = 0; part < 3; part++) {
            int j = tid + part * 384;
            if (j < 1024) {
                int r = j >> 3, c = j & 7;
                const __nv_bfloat16* src = (c < 4) ? Ah : Al;
                uint32_t sw = SWZ128((uint32_t)(r * 128 + c * 16));
                cpa16(SB + sw, src + (size_t)(m0 + r) * lda + kk + (c & 3) * 8);
            }
        }
        {
            const __nv_bfloat16 *bh, *bl; int kb, ldb;
            if (kk < KSPLIT) { bh = B1h; bl = B1l; kb = kk; ldb = ldb1; }
            else             { bh = B2h; bl = B2l; kb = kk - KSPLIT; ldb = ldb2; }
#pragma unroll
            for (int part = 0; part < 2; part++) {
                int j = tid + part * 384;
                if (j < 768) {
                    int r = j >> 3, c = j & 7;
                    const __nv_bfloat16* src = (c < 4) ? bh : bl;
                    uint32_t sw = SWZ128((uint32_t)(r * 128 + c * 16));
                    cpa16(SB + BOFS + sw, src + (size_t)(col0 + r) * ldb + kb + (c & 3) * 8);
                }
            }
        }
        asm volatile("cp.async.commit_group;\n" ::);
    };

    load_stage(0, 0);
    load_stage(1, 1);
#pragma unroll
    for (int kc = 0; kc < S; kc++) {
        int s = kc % 3;
        if (kc + 1 < S) { asm volatile("cp.async.wait_group 1;\n" ::); }
        else            { asm volatile("cp.async.wait_group 0;\n" ::); }
        __syncthreads();
        uint32_t SB = smB + (uint32_t)s * FSTG;
#pragma unroll
        for (int kt = 0; kt < 2; kt++) {
            uint32_t aH[2][4], aL[2][4], bH[2][4], bL[2][4];
#pragma unroll
            for (int mt = 0; mt < 2; mt++) {
                uint32_t row = (uint32_t)(wm*32 + mt*16 + (lane & 15));
                uint32_t ch = (uint32_t)(kt*2) + (uint32_t)(lane >> 4);
                ldsm4(aH[mt], SB + SWZ128(row*128u + ch*16u));
                ldsm4(aL[mt], SB + SWZ128(row*128u + (ch+4u)*16u));
            }
#pragma unroll
            for (int nt = 0; nt < 2; nt++) {
                uint32_t row = (uint32_t)(wn*32 + nt*16 + ((lane >> 4) << 3) + (lane & 7));
                uint32_t ch = (uint32_t)(kt*2) + ((uint32_t)(lane >> 3) & 1u);
                ldsm4(bH[nt], SB + BOFS + SWZ128(row*128u + ch*16u));
                ldsm4(bL[nt], SB + BOFS + SWZ128(row*128u + (ch+4u)*16u));
            }
#pragma unroll
            for (int mt = 0; mt < 2; mt++)
#pragma unroll
                for (int nt = 0; nt < 2; nt++) {
                    mma16816(acc[mt][nt*2],   aH[mt], &bH[nt][0]);
                    mma16816(acc[mt][nt*2+1], aH[mt], &bH[nt][2]);
                }
#pragma unroll
            for (int mt = 0; mt < 2; mt++)
#pragma unroll
                for (int nt = 0; nt < 2; nt++) {
                    mma16816(acc[mt][nt*2],   aH[mt], &bL[nt][0]);
                    mma16816(acc[mt][nt*2+1], aH[mt], &bL[nt][2]);
                }
#pragma unroll
            for (int mt = 0; mt < 2; mt++)
#pragma unroll
                for (int nt = 0; nt < 2; nt++) {
                    mma16816(acc[mt][nt*2],   aL[mt], &bH[nt][0]);
                    mma16816(acc[mt][nt*2+1], aL[mt], &bH[nt][2]);
                }
        }
        if (kc + 2 < S) load_stage((kc + 2) % 3, kc + 2);
    }
    __syncthreads();

    // ---- epilogue: regs -> smem transpose -> coalesced h/l stores ----
    float* sC = (float*)dsm;       // [96 cols][132 pad]
    int gid = lane >> 2, q = lane & 3;
#pragma unroll
    for (int mt = 0; mt < 2; mt++)
#pragma unroll
        for (int j = 0; j < 4; j++) {
            int ml = wm*32 + mt*16 + gid;
            int nl = wn*32 + j*8 + q*2;
            sC[nl*132 + ml]         = acc[mt][j][0];
            sC[(nl+1)*132 + ml]     = acc[mt][j][1];
            sC[nl*132 + ml + 8]     = acc[mt][j][2];
            sC[(nl+1)*132 + ml + 8] = acc[mt][j][3];
        }
    __syncthreads();
#pragma unroll
    for (int it = 0; it < 8; it++) {
        int w = it * 384 + tid;      // 3072 items: c(96) x chq(32)
        int c = w >> 5;
        int ch = (w & 31) << 2;
        int col = col0 + c;
        int bv = col >> 11;
        size_t ob = (size_t)col * ldc + m0 + ch;
        const float* sm = sC + c * 132 + ch;
        float4 vq = *(const float4*)sm;
        if (bias) {
            vq.x += bias[(m0 + ch + 0) * 12 + bv];
            vq.y += bias[(m0 + ch + 1) * 12 + bv];
            vq.z += bias[(m0 + ch + 2) * 12 + bv];
            vq.w += bias[(m0 + ch + 3) * 12 + bv];
        }
        __nv_bfloat16 h0 = __float2bfloat16(vq.x), h1 = __float2bfloat16(vq.y);
        __nv_bfloat16 h2 = __float2bfloat16(vq.z), h3 = __float2bfloat16(vq.w);
        *(__nv_bfloat162*)(Ch + ob)     = __halves2bfloat162(h0, h1);
        *(__nv_bfloat162*)(Ch + ob + 2) = __halves2bfloat162(h2, h3);
        *(__nv_bfloat162*)(Cl + ob) = __halves2bfloat162(
            __float2bfloat16(vq.x - __bfloat162float(h0)),
            __float2bfloat16(vq.y - __bfloat162float(h1)));
        *(__nv_bfloat162*)(Cl + ob + 2) = __halves2bfloat162(
            __float2bfloat16(vq.z - __bfloat162float(h2)),
            __float2bfloat16(vq.w - __bfloat162float(h3)));
    }
}

// ---------------- FUSED D-GEMM + VN-ReLU, templated K (full unroll) ----------------
// Column tile = 32 n-values x 3 vector comps (96 cols), warp tile 32x32.
template<int K>
__global__ __launch_bounds__(384, 2)
void hgemmF(const __nv_bfloat16* __restrict__ Ah, const __nv_bfloat16* __restrict__ Al,
            int lda,
            const __nv_bfloat16* __restrict__ Bh, const __nv_bfloat16* __restrict__ Bl, int ldb,
            const __nv_bfloat16* __restrict__ Xh, const __nv_bfloat16* __restrict__ Xl, int ldx,
            const float* __restrict__ pool,
            __nv_bfloat16* __restrict__ Yh, __nv_bfloat16* __restrict__ Yl, int ldy,
            const float* __restrict__ bias)
{
    extern __shared__ __align__(16) unsigned char dsm[];
    uint32_t smB = (uint32_t)__cvta_generic_to_shared(dsm);
    int tid = threadIdx.x, lane = tid & 31, wid = tid >> 5;
    int wm = wid & 3, wn = wid >> 2;
    int t = blockIdx.x;
    int bidx = t >> 6;
    int n0 = (t & 63) * 32;
    int m0 = blockIdx.y * 128;
    int colb = bidx * 6144 + n0;

    float acc[2][4][4];
#pragma unroll
    for (int a = 0; a < 2; a++)
#pragma unroll
        for (int b = 0; b < 4; b++)
#pragma unroll
            for (int c = 0; c < 4; c++) acc[a][b][c] = 0.f;

    constexpr int S = K >> 5;

    auto load_stage = [&](int s, int kc) {
        uint32_t SB = smB + (uint32_t)s * FSTG;
        int kk = kc << 5;
#pragma unroll
        for (int part = 0; part < 3; part++) {
            int j = tid + part * 384;
            if (j < 1024) {
                int r = j >> 3, c = j & 7;
                const __nv_bfloat16* src = (c < 4) ? Ah : Al;
                uint32_t sw = SWZ128((uint32_t)(r * 128 + c * 16));
                cpa16(SB + sw, src + (size_t)(m0 + r) * lda + kk + (c & 3) * 8);
            }
        }
#pragma unroll
        for (int part = 0; part < 2; part++) {
            int j = tid + part * 384;
            if (j < 768) {
                int r = j >> 3, c = j & 7;
                const __nv_bfloat16* src = (c < 4) ? Bh : Bl;
                int col = colb + ((r >> 5) << 11) + (r & 31);
                uint32_t sw = SWZ128((uint32_t)(r * 128 + c * 16));
                cpa16(SB + BOFS + sw, src + (size_t)col * ldb + kk + (c & 3) * 8);
            }
        }
        asm volatile("cp.async.commit_group;\n" ::);
    };

    load_stage(0, 0);
    load_stage(1, 1);
#pragma unroll
    for (int kc = 0; kc < S; kc++) {
        int s = kc % 3;
        if (kc + 1 < S) { asm volatile("cp.async.wait_group 1;\n" ::); }
        else            { asm volatile("cp.async.wait_group 0;\n" ::); }
        __syncthreads();
        uint32_t SB = smB + (uint32_t)s * FSTG;
#pragma unroll
        for (int kt = 0; kt < 2; kt++) {
            uint32_t aH[2][4], aL[2][4], bH[2][4], bL[2][4];
#pragma unroll
            for (int mt = 0; mt < 2; mt++) {
                uint32_t row = (uint32_t)(wm*32 + mt*16 + (lane & 15));
                uint32_t ch = (uint32_t)(kt*2) + (uint32_t)(lane >> 4);
                ldsm4(aH[mt], SB + SWZ128(row*128u + ch*16u));
                ldsm4(aL[mt], SB + SWZ128(row*128u + (ch+4u)*16u));
            }
#pragma unroll
            for (int nt = 0; nt < 2; nt++) {
                uint32_t row = (uint32_t)(wn*32 + nt*16 + ((lane >> 4) << 3) + (lane & 7));
                uint32_t ch = (uint32_t)(kt*2) + ((uint32_t)(lane >> 3) & 1u);
                ldsm4(bH[nt], SB + BOFS + SWZ128(row*128u + ch*16u));
                ldsm4(bL[nt], SB + BOFS + SWZ128(row*128u + (ch+4u)*16u));
            }
#pragma unroll
            for (int mt = 0; mt < 2; mt++)
#pragma unroll
                for (int nt = 0; nt < 2; nt++) {
                    mma16816(acc[mt][nt*2],   aH[mt], &bH[nt][0]);
                    mma16816(acc[mt][nt*2+1], aH[mt], &bH[nt][2]);
                }
#pragma unroll
            for (int mt = 0; mt < 2; mt++)
#pragma unroll
                for (int nt = 0; nt < 2; nt++) {
                    mma16816(acc[mt][nt*2],   aH[mt], &bL[nt][0]);
                    mma16816(acc[mt][nt*2+1], aH[mt], &bL[nt][2]);
                }
#pragma unroll
            for (int mt = 0; mt < 2; mt++)
#pragma unroll
                for (int nt = 0; nt < 2; nt++) {
                    mma16816(acc[mt][nt*2],   aL[mt], &bH[nt][0]);
                    mma16816(acc[mt][nt*2+1], aL[mt], &bH[nt][2]);
                }
        }
        if (kc + 2 < S) load_stage((kc + 2) % 3, kc + 2);
    }
    __syncthreads();

    // ---- epilogue: d -> smem, VN-ReLU across the 3 v planes, write Y h/l ----
    float* sC = (float*)dsm;   // [96 rows(v*32+nn)][132 pad]
    int gid = lane >> 2, q = lane & 3;
#pragma unroll
    for (int mt = 0; mt < 2; mt++)
#pragma unroll
        for (int j = 0; j < 4; j++) {
            int ml = wm*32 + mt*16 + gid;
            int nl = wn*32 + j*8 + q*2;
            sC[nl*132 + ml]         = acc[mt][j][0];
            sC[(nl+1)*132 + ml]     = acc[mt][j][1];
            sC[nl*132 + ml + 8]     = acc[mt][j][2];
            sC[(nl+1)*132 + ml + 8] = acc[mt][j][3];
        }
    __syncthreads();

    int bv0 = bidx * 3;
#pragma unroll
    for (int it = 0; it < 3; it++) {
        int w = it * 384 + tid;      // 1024 items: nn(32) x chq(32)
        if (w >= 1024) break;
        int nn = w >> 5;
        int ch = (w & 31) << 2;
        int mych = m0 + ch;
        float d[3][4], x[3][4];
#pragma unroll
        for (int v = 0; v < 3; v++) {
            const float* sm = sC + (v*32 + nn) * 132 + ch;
            d[v][0] = sm[0]; d[v][1] = sm[1]; d[v][2] = sm[2]; d[v][3] = sm[3];
            if (bias) {
#pragma unroll
                for (int j = 0; j < 4; j++) d[v][j] += bias[(mych + j) * 12 + bv0 + v];
            }
            int col = colb + v * 2048 + nn;
            if (pool != nullptr && mych >= 128) {
#pragma unroll
                for (int j = 0; j < 4; j++) x[v][j] = pool[(mych + j - 128) * 12 + bv0 + v];
            } else {
                size_t xo = (size_t)col * ldx + mych;
                __nv_bfloat162 h01 = *(const __nv_bfloat162*)(Xh + xo);
                __nv_bfloat162 h23 = *(const __nv_bfloat162*)(Xh + xo + 2);
                __nv_bfloat162 l01 = *(const __nv_bfloat162*)(Xl + xo);
                __nv_bfloat162 l23 = *(const __nv_bfloat162*)(Xl + xo + 2);
                x[v][0] = bfre(h01.x, l01.x); x[v][1] = bfre(h01.y, l01.y);
                x[v][2] = bfre(h23.x, l23.x); x[v][3] = bfre(h23.y, l23.y);
            }
        }
        float y[3][4];
#pragma unroll
        for (int j = 0; j < 4; j++) {
            float dot = x[0][j]*d[0][j] + x[1][j]*d[1][j] + x[2][j]*d[2][j];
            float dsq = d[0][j]*d[0][j] + d[1][j]*d[1][j] + d[2][j]*d[2][j] + 1e-8f;
            float tt = (dot >= 0.f) ? 0.f : dot / dsq;
            y[0][j] = x[0][j] - tt*d[0][j];
            y[1][j] = x[1][j] - tt*d[1][j];
            y[2][j] = x[2][j] - tt*d[2][j];
        }
#pragma unroll
        for (int v = 0; v < 3; v++) {
            size_t yo = (size_t)(colb + v * 2048 + nn) * ldy + mych;
            __nv_bfloat16 h0 = __float2bfloat16(y[v][0]), h1 = __float2bfloat16(y[v][1]);
            __nv_bfloat16 h2 = __float2bfloat16(y[v][2]), h3 = __float2bfloat16(y[v][3]);
            *(__nv_bfloat162*)(Yh + yo)     = __halves2bfloat162(h0, h1);
            *(__nv_bfloat162*)(Yh + yo + 2) = __halves2bfloat162(h2, h3);
            *(__nv_bfloat162*)(Yl + yo) = __halves2bfloat162(
                __float2bfloat16(y[v][0] - __bfloat162float(h0)),
                __float2bfloat16(y[v][1] - __bfloat162float(h1)));
            *(__nv_bfloat162*)(Yl + yo + 2) = __halves2bfloat162(
                __float2bfloat16(y[v][2] - __bfloat162float(h2)),
                __float2bfloat16(y[v][3] - __bfloat162float(h3)));
        }
    }
}

// ---------------- mean over N (reads h/l, vectorized) ----------------
__global__ __launch_bounds__(256) void poolpart(const __nv_bfloat16* __restrict__ Nh,
                                                const __nv_bfloat16* __restrict__ Nl,
                                                float* __restrict__ part) {
    __shared__ float red[512];
    int bv = blockIdx.x, chunk = blockIdx.y;
    int tid = threadIdx.x;
    int c2 = (tid & 63) << 1;       // channel pair
    int ns = tid >> 6;              // 0..3
    float s0 = 0.f, s1 = 0.f;
    int base = bv * 2048 + chunk * 128 + ns * 32;
    for (int n = 0; n < 32; n++) {
        size_t idx = (size_t)(base + n) * 128 + c2;
        __nv_bfloat162 h = *(const __nv_bfloat162*)(Nh + idx);
        __nv_bfloat162 l = *(const __nv_bfloat162*)(Nl + idx);
        s0 += __bfloat162float(h.x) + __bfloat162float(l.x);
        s1 += __bfloat162float(h.y) + __bfloat162float(l.y);
    }
    red[ns * 128 + c2]     = s0;
    red[ns * 128 + c2 + 1] = s1;
    __syncthreads();
    if (tid < 128) {
        float s = red[tid] + red[128 + tid] + red[256 + tid] + red[384 + tid];
        part[(chunk * 128 + tid) * 12 + bv] = s;
    }
}
__global__ __launch_bounds__(256) void poolred(const float* __restrict__ part,
                                               float* __restrict__ out) {
    int idx = blockIdx.x * 256 + threadIdx.x;
    if (idx >= 1536) return;
    int c = idx / 12, bv = idx - c * 12;
    float s = 0.f;
    for (int ch = 0; ch < 16; ch++) s += part[(ch * 128 + c) * 12 + bv];
    out[c * 12 + bv] = s * (1.f / 2048.f);
}

// ---------------- combined rank-12 projections (PD0 + PWS), 36 blocks x 128 ----------------
__global__ __launch_bounds__(128) void proj2(const float* __restrict__ d0w,
                                             const float* __restrict__ Wsw,
                                             const float* __restrict__ pl,
                                             float* __restrict__ PD0,
                                             float* __restrict__ PWS) {
    int idx = blockIdx.x * 128 + threadIdx.x;
    if (idx >= 4608) return;     // 384 * 12
    int o = idx / 12, bv = idx - o * 12;
    const float* Ar; float* outp; int oo = o;
    if (o < 256) { Ar = d0w + o * 256 + 128; outp = PD0; }
    else         { oo = o - 256; Ar = Wsw + oo * 256 + 128; outp = PWS; }
    float s = 0.f;
#pragma unroll 4
    for (int c = 0; c < 128; c++) s += Ar[c] * pl[c * 12 + bv];
    outp[oo * 12 + bv] = s;
}

// ---------------- final head ----------------
__global__ __launch_bounds__(512) void final_head(const float* __restrict__ PF,
                                                  const float* __restrict__ act_d,
                                                  const float* __restrict__ fc_c,
                                                  float* __restrict__ out) {
    __shared__ float spf[1536], sd[1536], sy[1536];
    int tid = threadIdx.x;
    for (int i = tid; i < 1536; i += 512) spf[i] = PF[i];
    __syncthreads();
    for (int i = tid; i < 1536; i += 512) {
        int o = i / 12, bv = i - o * 12;
        float s = 0.f;
        for (int c = 0; c < 128; c++) s += act_d[o*128 + c] * spf[c*12 + bv];
        sd[i] = s;
    }
    __syncthreads();
    {
        int o = tid >> 2, b = tid & 3;
        int base = o * 12 + b * 3;
        float x0 = spf[base], x1 = spf[base+1], x2 = spf[base+2];
        float d0 = sd[base],  d1 = sd[base+1],  d2 = sd[base+2];
        float dot = x0*d0 + x1*d1 + x2*d2;
        float dsq = d0*d0 + d1*d1 + d2*d2 + 1e-8f;
        float t = (dot >= 0.f) ? 0.f : dot / dsq;
        sy[base]   = x0 - t*d0;
        sy[base+1] = x1 - t*d1;
        sy[base+2] = x2 - t*d2;
    }
    __syncthreads();
    for (int i = tid; i < 1536; i += 512) {
        int o = i / 12, bv = i - o * 12;
        int b = bv / 3, v = bv - b * 3;
        float s = 0.f;
        for (int c = 0; c < 128; c++) s += fc_c[o*128 + c] * sy[c*12 + bv];
        out[b * 384 + o * 3 + v] = s;
    }
}

// ---------------- launcher ----------------
extern "C" void kernel_launch(void* const* d_in, const int* in_sizes, int n_in,
                              void* d_out, int out_size) {
    const float* p        = (const float*)d_in[0];
    const float* fc_pos_W = (const float*)d_in[1];
    const float* blk_d0   = (const float*)d_in[2];
    const float* blk_W0   = (const float*)d_in[3];
    const float* blk_d1   = (const float*)d_in[4];
    const float* blk_W1   = (const float*)d_in[5];
    const float* blk_Ws   = (const float*)d_in[6];
    const float* fc_c_W   = (const float*)d_in[7];
    const float* act_d    = (const float*)d_in[8];
    float* out = (float*)d_out;

    const size_t SMM = 86016;   // 3 x 28672
    cudaFuncSetAttribute(hgemm<256,256>, cudaFuncAttributeMaxDynamicSharedMemorySize, SMM);
    cudaFuncSetAttribute(hgemm<384,256>, cudaFuncAttributeMaxDynamicSharedMemorySize, SMM);
    cudaFuncSetAttribute(hgemm<128,128>, cudaFuncAttributeMaxDynamicSharedMemorySize, SMM);
    cudaFuncSetAttribute(hgemm<256,128>, cudaFuncAttributeMaxDynamicSharedMemorySize, SMM);
    cudaFuncSetAttribute(hgemmF<256>,    cudaFuncAttributeMaxDynamicSharedMemorySize, SMM);
    cudaFuncSetAttribute(hgemmF<128>,    cudaFuncAttributeMaxDynamicSharedMemorySize, SMM);
    cudaFuncSetAttribute(knn_mean4, cudaFuncAttributeMaxDynamicSharedMemorySize, 57344);

    float *MEAN, *POOL, *PPART, *PD0, *PWS;
    __nv_bfloat16 *XIN0h, *XIN0l, *Yh, *Yl, *Hh, *Hl, *Y2h, *Y2l, *N0h, *N0l, *N1h, *N1l, *Wh, *Wl;
    cudaGetSymbolAddress((void**)&MEAN, g_mean);
    cudaGetSymbolAddress((void**)&POOL, g_pool);
    cudaGetSymbolAddress((void**)&PPART, g_ppart);
    cudaGetSymbolAddress((void**)&PD0, g_Pd0);
    cudaGetSymbolAddress((void**)&PWS, g_PWs);
    cudaGetSymbolAddress((void**)&XIN0h, g_XIN0h);
    cudaGetSymbolAddress((void**)&XIN0l, g_XIN0l);
    cudaGetSymbolAddress((void**)&Yh, g_Yh);
    cudaGetSymbolAddress((void**)&Yl, g_Yl);
    cudaGetSymbolAddress((void**)&Hh, g_Hh);
    cudaGetSymbolAddress((void**)&Hl, g_Hl);
    cudaGetSymbolAddress((void**)&Y2h, g_Y2h);
    cudaGetSymbolAddress((void**)&Y2l, g_Y2l);
    cudaGetSymbolAddress((void**)&N0h, g_N0h);
    cudaGetSymbolAddress((void**)&N0l, g_N0l);
    cudaGetSymbolAddress((void**)&N1h, g_N1h);
    cudaGetSymbolAddress((void**)&N1l, g_N1l);
    cudaGetSymbolAddress((void**)&Wh, g_Wh);
    cudaGetSymbolAddress((void**)&Wl, g_Wl);

    splitall<<<2944, 256>>>(blk_d0, blk_W0, blk_d1, blk_W1, blk_Ws, Wh, Wl);
    knn_mean4<<<2048, 256, 57344>>>(p, MEAN);
    feat_t<<<NCOLS / 8, 256>>>(p, MEAN, fc_pos_W, XIN0h, XIN0l);

    const dim3 GF1(256, 1), GF2(256, 2), G1(256, 1);

    // ---- block 0 ----
    hgemmF<256><<<GF2, 384, SMM>>>(Wh+OFF_D0, Wl+OFF_D0, 256,
                                   XIN0h, XIN0l, 256, XIN0h, XIN0l, 256, nullptr,
                                   Yh, Yl, 256, nullptr);
    hgemm<256,256><<<G1, 384, SMM>>>(Wh+OFF_W0, Wl+OFF_W0, 256,
                                     Yh, Yl, 256, Yh, Yl, 256, Hh, Hl, 128, nullptr);
    hgemmF<128><<<GF1, 384, SMM>>>(Wh+OFF_D1, Wl+OFF_D1, 128,
                                   Hh, Hl, 128, Hh, Hl, 128, nullptr,
                                   Y2h, Y2l, 128, nullptr);
    hgemm<384,256><<<G1, 384, SMM>>>(Wh+OFF_SW0, Wl+OFF_SW0, 384,
                                     XIN0h, XIN0l, 256, Y2h, Y2l, 128, N1h, N1l, 128, nullptr);

    // ---- blocks 1..4 ----
    __nv_bfloat16 *NINh = N1h, *NINl = N1l, *NOh = N0h, *NOl = N0l;
    for (int i = 1; i < 5; i++) {
        int swoff = OFF_SWI + (i - 1) * 32768;
        poolpart<<<dim3(12, 16), 256>>>(NINh, NINl, PPART);
        poolred<<<6, 256>>>(PPART, POOL);
        proj2<<<36, 128>>>(blk_d0 + i * 65536, blk_Ws + i * 32768, POOL, PD0, PWS);

        hgemmF<128><<<GF2, 384, SMM>>>(Wh+OFF_D0+i*65536, Wl+OFF_D0+i*65536, 256,
                                       NINh, NINl, 128, NINh, NINl, 128, POOL,
                                       Yh, Yl, 256, PD0);
        hgemm<256,256><<<G1, 384, SMM>>>(Wh+OFF_W0+i*32768, Wl+OFF_W0+i*32768, 256,
                                         Yh, Yl, 256, Yh, Yl, 256, Hh, Hl, 128, nullptr);
        hgemmF<128><<<GF1, 384, SMM>>>(Wh+OFF_D1+i*16384, Wl+OFF_D1+i*16384, 128,
                                       Hh, Hl, 128, Hh, Hl, 128, nullptr,
                                       Y2h, Y2l, 128, nullptr);
        hgemm<256,128><<<G1, 384, SMM>>>(Wh+swoff, Wl+swoff, 256,
                                         NINh, NINl, 128, Y2h, Y2l, 128, NOh, NOl, 128, PWS);

        __nv_bfloat16* tb;
        tb = NINh; NINh = NOh; NOh = tb;
        tb = NINl; NINl = NOl; NOl = tb;
    }

    // ---- final pooling + head ----
    poolpart<<<dim3(12, 16), 256>>>(NINh, NINl, PPART);
    poolred<<<6, 256>>>(PPART, POOL);
    final_head<<<1, 512>>>(POOL, act_d, fc_c_W, out);
}

// round 15
// speedup vs baseline: 1.0214x; 1.0214x over previous
#include <cuda_runtime.h>
#include <cuda_bf16.h>
#include <cstdint>

#define NCOLS 24576   // B*3*N = 4*3*2048
#define NPTS  2048
#define BATCH 4
#define KNN   20

// ---------------- static scratch (bf16 hi/lo activations, [col][channel]) ----------------
__device__ __nv_bfloat16 g_XIN0h[6291456], g_XIN0l[6291456];   // [24576][256]
__device__ __nv_bfloat16 g_Yh[6291456],   g_Yl[6291456];       // [24576][256]
__device__ __nv_bfloat16 g_Hh[3145728],   g_Hl[3145728];       // [24576][128]
__device__ __nv_bfloat16 g_Y2h[3145728],  g_Y2l[3145728];
__device__ __nv_bfloat16 g_N0h[3145728],  g_N0l[3145728];
__device__ __nv_bfloat16 g_N1h[3145728],  g_N1l[3145728];
__device__ __nv_bfloat16 g_Wh[819200],    g_Wl[819200];
__device__ float g_mean[BATCH * NPTS * 3];
__device__ float g_poolsum[128 * 12];     // un-normalized column sums (x2048)
__device__ float g_Pd0[256 * 12];
__device__ float g_PWs[128 * 12];

// weight regions inside g_Wh/g_Wl
#define OFF_D0  0         // 5 x 256x256
#define OFF_W0  327680    // 5 x 128x256
#define OFF_D1  491520    // 5 x 128x128
#define OFF_SW0 573440    // block0 [Ws|W1] 128x384
#define OFF_SWI 622592    // blocks1-4 [Ws[:, :128]|W1] 128x256 each

#define INV_N (1.f / 2048.f)

// ---------------- ptx helpers ----------------
__device__ __forceinline__ void cpa16(uint32_t dst, const void* src) {
    asm volatile("cp.async.cg.shared.global [%0], [%1], 16;\n" :: "r"(dst), "l"(src));
}
__device__ __forceinline__ void ldsm4(uint32_t* r, uint32_t addr) {
    asm volatile("ldmatrix.sync.aligned.m8n8.x4.shared.b16 {%0,%1,%2,%3}, [%4];"
                 : "=r"(r[0]), "=r"(r[1]), "=r"(r[2]), "=r"(r[3]) : "r"(addr));
}
__device__ __forceinline__ void mma16816(float* c, const uint32_t* a, const uint32_t* b) {
    asm volatile("mma.sync.aligned.m16n8k16.row.col.f32.bf16.bf16.f32 "
                 "{%0,%1,%2,%3}, {%4,%5,%6,%7}, {%8,%9}, {%0,%1,%2,%3};"
                 : "+f"(c[0]), "+f"(c[1]), "+f"(c[2]), "+f"(c[3])
                 : "r"(a[0]), "r"(a[1]), "r"(a[2]), "r"(a[3]), "r"(b[0]), "r"(b[1]));
}
__device__ __forceinline__ float bfre(__nv_bfloat16 h, __nv_bfloat16 l) {
    return __bfloat162float(h) + __bfloat162float(l);
}

// SW128 swizzle: bits[6:4] ^= bits[9:7] (conflict-free ldsm on 128B rows)
#define SWZ128(x) ((x) ^ (((x) >> 3) & 0x70))

// stage: A[128 rows][128B: hi 64 | lo 64] 16384B, then B[96 rows][128B] 12288B
#define FSTG 28672u
#define BOFS 16384u

// ---------------- all weight splits in ONE launch ----------------
__global__ __launch_bounds__(256) void splitall(const float* __restrict__ d0,
                                                const float* __restrict__ W0,
                                                const float* __restrict__ d1,
                                                const float* __restrict__ W1,
                                                const float* __restrict__ Ws,
                                                __nv_bfloat16* __restrict__ Wh,
                                                __nv_bfloat16* __restrict__ Wl) {
    int i = blockIdx.x * 256 + threadIdx.x;
    float x; int di;
    if (i < 327680) { x = d0[i]; di = OFF_D0 + i; }
    else if (i < 491520) { int j = i - 327680; x = W0[j]; di = OFF_W0 + j; }
    else if (i < 573440) { int j = i - 491520; x = d1[j]; di = OFF_D1 + j; }
    else if (i < 622592) {
        int j = i - 573440; int m = j / 384, k = j - m * 384;
        x = (k < 256) ? Ws[m*256 + k] : W1[m*128 + (k - 256)];
        di = OFF_SW0 + j;
    } else if (i < 753664) {
        int j = i - 622592; int blk = j >> 15; int jj = j & 32767;
        int m = jj >> 8, k = jj & 255;
        x = (k < 128) ? Ws[(blk+1)*32768 + m*256 + k] : W1[(blk+1)*16384 + m*128 + (k-128)];
        di = OFF_SWI + j;
    } else return;
    __nv_bfloat16 h = __float2bfloat16(x);
    Wh[di] = h;
    Wl[di] = __float2bfloat16(x - __bfloat162float(h));
}

// ---------------- KNN mean: 4 queries per block, 2 warps per query ----------------
__global__ __launch_bounds__(256) void knn_mean4(const float* __restrict__ p,
                                                 float* __restrict__ outm) {
    extern __shared__ float sm[];
    float* sx = sm;              // 2048
    float* sy = sm + 2048;
    float* sz = sm + 4096;
    float* sd = sm + 6144;       // 4 x 2048
    __shared__ float swv[4][2];
    __shared__ int   swi[4][2];
    __shared__ float sacc[4][3];
    int blk = blockIdx.x;        // 0..2047
    int b = blk >> 9;            // 512 blocks per batch
    int q0 = (blk & 511) * 4;    // base query index within batch
    int tid = threadIdx.x;
    const float* pb = p + b * NPTS * 3;
    for (int i = tid; i < NPTS; i += 256) {
        sx[i] = pb[i*3+0]; sy[i] = pb[i*3+1]; sz[i] = pb[i*3+2];
    }
    if (tid < 4) { sacc[tid][0] = 0.f; sacc[tid][1] = 0.f; sacc[tid][2] = 0.f; }
    __syncthreads();
    float qx[4], qy[4], qz[4], qq[4];
#pragma unroll
    for (int qi = 0; qi < 4; qi++) {
        int n = q0 + qi;
        qx[qi] = sx[n]; qy[qi] = sy[n]; qz[qi] = sz[n];
        qq[qi] = qx[qi]*qx[qi] + qy[qi]*qy[qi] + qz[qi]*qz[qi];
    }
    for (int i = tid; i < NPTS; i += 256) {
        float x = sx[i], y = sy[i], z = sz[i];
        float xx = x*x + y*y + z*z;
#pragma unroll
        for (int qi = 0; qi < 4; qi++)
            sd[qi*2048 + i] = 2.f*(qx[qi]*x + qy[qi]*y + qz[qi]*z) - qq[qi] - xx;
    }
    __syncthreads();
    int w = tid >> 5, lane = tid & 31;
    int myq = w >> 1, half = w & 1;
    float* sdq = sd + myq * 2048;
    for (int r = 0; r < KNN; r++) {
        float bv = -3.4e38f; int bi = 1 << 30;
#pragma unroll 4
        for (int j = 0; j < 32; j++) {
            int i = half*1024 + j*32 + lane;
            float v = sdq[i];
            if (v > bv) { bv = v; bi = i; }        // ascending i -> smallest idx wins ties
        }
        for (int off = 16; off; off >>= 1) {
            float ov = __shfl_down_sync(0xffffffffu, bv, off);
            int   oi = __shfl_down_sync(0xffffffffu, bi, off);
            if (ov > bv || (ov == bv && oi < bi)) { bv = ov; bi = oi; }
        }
        if (lane == 0) { swv[myq][half] = bv; swi[myq][half] = bi; }
        __syncthreads();
        if (lane == 0 && half == 0) {
            float v0 = swv[myq][0], v1 = swv[myq][1];
            int   i0 = swi[myq][0], i1 = swi[myq][1];
            int bj = (v0 > v1 || (v0 == v1 && i0 < i1)) ? i0 : i1;
            sacc[myq][0] += sx[bj];
            sacc[myq][1] += sy[bj];
            sacc[myq][2] += sz[bj];
            sdq[bj] = -3.4e38f;
        }
        __syncthreads();
    }
    if (tid < 4) {
        int gid = b * NPTS + q0 + tid;
        const float inv = 1.f / KNN;
        outm[gid*3+0] = sacc[tid][0] * inv;
        outm[gid*3+1] = sacc[tid][1] * inv;
        outm[gid*3+2] = sacc[tid][2] * inv;
    }
}

// ------------- feat: out[col][256] bf16 hi/lo -------------
__global__ __launch_bounds__(256) void feat_t(const float* __restrict__ p,
                                              const float* __restrict__ m,
                                              const float* __restrict__ W,
                                              __nv_bfloat16* __restrict__ Xh,
                                              __nv_bfloat16* __restrict__ Xl) {
    __shared__ float sW[768];
    int tid = threadIdx.x;
    for (int i = tid; i < 768; i += 256) sW[i] = W[i];
    __syncthreads();
    int wid = tid >> 5, lane = tid & 31;
    int col = blockIdx.x * 8 + wid;
    int b = col / 6144;
    int rem = col - b * 6144;
    int v = rem >> 11;
    int n = rem & 2047;
    int pi = (b * NPTS + n) * 3;
    float px = p[pi], py = p[pi+1], pz = p[pi+2];
    float mx = m[pi], my = m[pi+1], mz = m[pi+2];
    float pv, mv, cv;
    if (v == 0)      { pv = px; mv = mx; cv = my*pz - mz*py; }
    else if (v == 1) { pv = py; mv = my; cv = mz*px - mx*pz; }
    else             { pv = pz; mv = mz; cv = mx*py - my*px; }
#pragma unroll
    for (int j = 0; j < 8; j++) {
        int o = j * 32 + lane;
        float r = sW[o*3]*(mv - pv) + sW[o*3+1]*pv + sW[o*3+2]*cv;
        size_t idx = (size_t)col * 256 + o;
        __nv_bfloat16 h = __float2bfloat16(r);
        Xh[idx] = h;
        Xl[idx] = __float2bfloat16(r - __bfloat162float(h));
    }
}

// ---------------- plain split-bf16 HMMA GEMM, 384 threads, swizzled smem ----------------
// BM=128, BN=96, BK=32; warp tile 32x32; 3-stage pipeline; SW128 conflict-free layout.
// Optional poolAcc: epilogue accumulates un-normalized column sums of C into poolAcc[ch*12+bv].
__global__ __launch_bounds__(384, 2)
void hgemm(const __nv_bfloat16* __restrict__ Ah, const __nv_bfloat16* __restrict__ Al,
           int lda, int K, int Ksplit,
           const __nv_bfloat16* __restrict__ B1h, const __nv_bfloat16* __restrict__ B1l, int ldb1,
           const __nv_bfloat16* __restrict__ B2h, const __nv_bfloat16* __restrict__ B2l, int ldb2,
           __nv_bfloat16* __restrict__ Ch, __nv_bfloat16* __restrict__ Cl, int ldc,
           const float* __restrict__ bias,
           float* __restrict__ poolAcc)
{
    extern __shared__ __align__(16) unsigned char dsm[];
    uint32_t smB = (uint32_t)__cvta_generic_to_shared(dsm);
    int tid = threadIdx.x, lane = tid & 31, wid = tid >> 5;
    int wm = wid & 3, wn = wid >> 2;          // wm 0..3, wn 0..2
    int col0 = blockIdx.x * 96, m0 = blockIdx.y * 128;

    float acc[2][4][4];
#pragma unroll
    for (int a = 0; a < 2; a++)
#pragma unroll
        for (int b = 0; b < 4; b++)
#pragma unroll
            for (int c = 0; c < 4; c++) acc[a][b][c] = 0.f;

    int S = K >> 5;

    auto load_stage = [&](int s, int kc) {
        uint32_t SB = smB + (uint32_t)s * FSTG;
        int kk = kc << 5;
#pragma unroll
        for (int part = 0; part < 3; part++) {
            int j = tid + part * 384;
            if (j < 1024) {
                int r = j >> 3, c = j & 7;
                const __nv_bfloat16* src = (c < 4) ? Ah : Al;
                uint32_t sw = SWZ128((uint32_t)(r * 128 + c * 16));
                cpa16(SB + sw, src + (size_t)(m0 + r) * lda + kk + (c & 3) * 8);
            }
        }
        {
            const __nv_bfloat16 *bh, *bl; int kb, ldb;
            if (kk < Ksplit) { bh = B1h; bl = B1l; kb = kk; ldb = ldb1; }
            else             { bh = B2h; bl = B2l; kb = kk - Ksplit; ldb = ldb2; }
#pragma unroll
            for (int part = 0; part < 2; part++) {
                int j = tid + part * 384;
                if (j < 768) {
                    int r = j >> 3, c = j & 7;
                    const __nv_bfloat16* src = (c < 4) ? bh : bl;
                    uint32_t sw = SWZ128((uint32_t)(r * 128 + c * 16));
                    cpa16(SB + BOFS + sw, src + (size_t)(col0 + r) * ldb + kb + (c & 3) * 8);
                }
            }
        }
        asm volatile("cp.async.commit_group;\n" ::);
    };

    load_stage(0, 0);
    load_stage(1, 1);
    for (int kc = 0; kc < S; kc++) {
        int s = kc % 3;
        if (kc + 1 < S) { asm volatile("cp.async.wait_group 1;\n" ::); }
        else            { asm volatile("cp.async.wait_group 0;\n" ::); }
        __syncthreads();
        uint32_t SB = smB + (uint32_t)s * FSTG;
#pragma unroll
        for (int kt = 0; kt < 2; kt++) {
            uint32_t aH[2][4], aL[2][4], bH[2][4], bL[2][4];
#pragma unroll
            for (int mt = 0; mt < 2; mt++) {
                uint32_t row = (uint32_t)(wm*32 + mt*16 + (lane & 15));
                uint32_t ch = (uint32_t)(kt*2) + (uint32_t)(lane >> 4);
                ldsm4(aH[mt], SB + SWZ128(row*128u + ch*16u));
                ldsm4(aL[mt], SB + SWZ128(row*128u + (ch+4u)*16u));
            }
#pragma unroll
            for (int nt = 0; nt < 2; nt++) {
                uint32_t row = (uint32_t)(wn*32 + nt*16 + ((lane >> 4) << 3) + (lane & 7));
                uint32_t ch = (uint32_t)(kt*2) + ((uint32_t)(lane >> 3) & 1u);
                ldsm4(bH[nt], SB + BOFS + SWZ128(row*128u + ch*16u));
                ldsm4(bL[nt], SB + BOFS + SWZ128(row*128u + (ch+4u)*16u));
            }
#pragma unroll
            for (int mt = 0; mt < 2; mt++)
#pragma unroll
                for (int nt = 0; nt < 2; nt++) {
                    mma16816(acc[mt][nt*2],   aH[mt], &bH[nt][0]);
                    mma16816(acc[mt][nt*2+1], aH[mt], &bH[nt][2]);
                }
#pragma unroll
            for (int mt = 0; mt < 2; mt++)
#pragma unroll
                for (int nt = 0; nt < 2; nt++) {
                    mma16816(acc[mt][nt*2],   aH[mt], &bL[nt][0]);
                    mma16816(acc[mt][nt*2+1], aH[mt], &bL[nt][2]);
                }
#pragma unroll
            for (int mt = 0; mt < 2; mt++)
#pragma unroll
                for (int nt = 0; nt < 2; nt++) {
                    mma16816(acc[mt][nt*2],   aL[mt], &bH[nt][0]);
                    mma16816(acc[mt][nt*2+1], aL[mt], &bH[nt][2]);
                }
        }
        if (kc + 2 < S) load_stage((kc + 2) % 3, kc + 2);
    }
    __syncthreads();

    // ---- epilogue: regs -> smem transpose -> coalesced h/l stores (+ optional pool acc) ----
    float* sC = (float*)dsm;       // [96 cols][132 pad]
    int gid = lane >> 2, q = lane & 3;
#pragma unroll
    for (int mt = 0; mt < 2; mt++)
#pragma unroll
        for (int j = 0; j < 4; j++) {
            int ml = wm*32 + mt*16 + gid;
            int nl = wn*32 + j*8 + q*2;
            sC[nl*132 + ml]         = acc[mt][j][0];
            sC[(nl+1)*132 + ml]     = acc[mt][j][1];
            sC[nl*132 + ml + 8]     = acc[mt][j][2];
            sC[(nl+1)*132 + ml + 8] = acc[mt][j][3];
        }
    __syncthreads();
    int bv0 = col0 >> 11;
    int bvLast = (col0 + 95) >> 11;
    bool cross = (bvLast != bv0);
    float ps0[4] = {0.f, 0.f, 0.f, 0.f};
    float ps1[4] = {0.f, 0.f, 0.f, 0.f};
#pragma unroll
    for (int it = 0; it < 8; it++) {
        int w = it * 384 + tid;      // 3072 items: c(96) x chq(32); ch fixed per thread
        int c = w >> 5;
        int ch = (w & 31) << 2;
        int col = col0 + c;
        int bv = col >> 11;
        size_t ob = (size_t)col * ldc + m0 + ch;
        const float* sm = sC + c * 132 + ch;
        float4 vq = *(const float4*)sm;
        if (bias) {
            vq.x += bias[(m0 + ch + 0) * 12 + bv];
            vq.y += bias[(m0 + ch + 1) * 12 + bv];
            vq.z += bias[(m0 + ch + 2) * 12 + bv];
            vq.w += bias[(m0 + ch + 3) * 12 + bv];
        }
        if (poolAcc) {
            float* pt = (bv == bv0) ? ps0 : ps1;
            pt[0] += vq.x; pt[1] += vq.y; pt[2] += vq.z; pt[3] += vq.w;
        }
        __nv_bfloat16 h0 = __float2bfloat16(vq.x), h1 = __float2bfloat16(vq.y);
        __nv_bfloat16 h2 = __float2bfloat16(vq.z), h3 = __float2bfloat16(vq.w);
        *(__nv_bfloat162*)(Ch + ob)     = __halves2bfloat162(h0, h1);
        *(__nv_bfloat162*)(Ch + ob + 2) = __halves2bfloat162(h2, h3);
        *(__nv_bfloat162*)(Cl + ob) = __halves2bfloat162(
            __float2bfloat16(vq.x - __bfloat162float(h0)),
            __float2bfloat16(vq.y - __bfloat162float(h1)));
        *(__nv_bfloat162*)(Cl + ob + 2) = __halves2bfloat162(
            __float2bfloat16(vq.z - __bfloat162float(h2)),
            __float2bfloat16(vq.w - __bfloat162float(h3)));
    }
    if (poolAcc) {
        float* sP = sC + 96 * 132;   // 256 floats of scratch
        __syncthreads();
        for (int i = tid; i < 256; i += 384) sP[i] = 0.f;
        __syncthreads();
        int ch = (tid & 31) << 2;
#pragma unroll
        for (int j = 0; j < 4; j++) atomicAdd(&sP[ch + j], ps0[j]);
        if (cross) {
#pragma unroll
            for (int j = 0; j < 4; j++) atomicAdd(&sP[128 + ch + j], ps1[j]);
        }
        __syncthreads();
        if (tid < 128) {
            atomicAdd(&poolAcc[tid * 12 + bv0], sP[tid]);
            if (cross) atomicAdd(&poolAcc[tid * 12 + bvLast], sP[128 + tid]);
        }
    }
}

// ---------------- FUSED D-GEMM + VN-ReLU, 384 threads, swizzled smem ----------------
// Column tile = 32 n-values x 3 vector comps (96 cols), warp tile 32x32.
// pool (if non-null) holds UN-NORMALIZED sums; scaled by 1/2048 at read.
__global__ __launch_bounds__(384, 2)
void hgemmF(const __nv_bfloat16* __restrict__ Ah, const __nv_bfloat16* __restrict__ Al,
            int lda, int K,
            const __nv_bfloat16* __restrict__ Bh, const __nv_bfloat16* __restrict__ Bl, int ldb,
            const __nv_bfloat16* __restrict__ Xh, const __nv_bfloat16* __restrict__ Xl, int ldx,
            const float* __restrict__ pool,
            __nv_bfloat16* __restrict__ Yh, __nv_bfloat16* __restrict__ Yl, int ldy,
            const float* __restrict__ bias)
{
    extern __shared__ __align__(16) unsigned char dsm[];
    uint32_t smB = (uint32_t)__cvta_generic_to_shared(dsm);
    int tid = threadIdx.x, lane = tid & 31, wid = tid >> 5;
    int wm = wid & 3, wn = wid >> 2;
    int t = blockIdx.x;
    int bidx = t >> 6;
    int n0 = (t & 63) * 32;
    int m0 = blockIdx.y * 128;
    int colb = bidx * 6144 + n0;

    float acc[2][4][4];
#pragma unroll
    for (int a = 0; a < 2; a++)
#pragma unroll
        for (int b = 0; b < 4; b++)
#pragma unroll
            for (int c = 0; c < 4; c++) acc[a][b][c] = 0.f;

    int S = K >> 5;

    auto load_stage = [&](int s, int kc) {
        uint32_t SB = smB + (uint32_t)s * FSTG;
        int kk = kc << 5;
#pragma unroll
        for (int part = 0; part < 3; part++) {
            int j = tid + part * 384;
            if (j < 1024) {
                int r = j >> 3, c = j & 7;
                const __nv_bfloat16* src = (c < 4) ? Ah : Al;
                uint32_t sw = SWZ128((uint32_t)(r * 128 + c * 16));
                cpa16(SB + sw, src + (size_t)(m0 + r) * lda + kk + (c & 3) * 8);
            }
        }
#pragma unroll
        for (int part = 0; part < 2; part++) {
            int j = tid + part * 384;
            if (j < 768) {
                int r = j >> 3, c = j & 7;
                const __nv_bfloat16* src = (c < 4) ? Bh : Bl;
                int col = colb + ((r >> 5) << 11) + (r & 31);
                uint32_t sw = SWZ128((uint32_t)(r * 128 + c * 16));
                cpa16(SB + BOFS + sw, src + (size_t)col * ldb + kk + (c & 3) * 8);
            }
        }
        asm volatile("cp.async.commit_group;\n" ::);
    };

    load_stage(0, 0);
    load_stage(1, 1);
    for (int kc = 0; kc < S; kc++) {
        int s = kc % 3;
        if (kc + 1 < S) { asm volatile("cp.async.wait_group 1;\n" ::); }
        else            { asm volatile("cp.async.wait_group 0;\n" ::); }
        __syncthreads();
        uint32_t SB = smB + (uint32_t)s * FSTG;
#pragma unroll
        for (int kt = 0; kt < 2; kt++) {
            uint32_t aH[2][4], aL[2][4], bH[2][4], bL[2][4];
#pragma unroll
            for (int mt = 0; mt < 2; mt++) {
                uint32_t row = (uint32_t)(wm*32 + mt*16 + (lane & 15));
                uint32_t ch = (uint32_t)(kt*2) + (uint32_t)(lane >> 4);
                ldsm4(aH[mt], SB + SWZ128(row*128u + ch*16u));
                ldsm4(aL[mt], SB + SWZ128(row*128u + (ch+4u)*16u));
            }
#pragma unroll
            for (int nt = 0; nt < 2; nt++) {
                uint32_t row = (uint32_t)(wn*32 + nt*16 + ((lane >> 4) << 3) + (lane & 7));
                uint32_t ch = (uint32_t)(kt*2) + ((uint32_t)(lane >> 3) & 1u);
                ldsm4(bH[nt], SB + BOFS + SWZ128(row*128u + ch*16u));
                ldsm4(bL[nt], SB + BOFS + SWZ128(row*128u + (ch+4u)*16u));
            }
#pragma unroll
            for (int mt = 0; mt < 2; mt++)
#pragma unroll
                for (int nt = 0; nt < 2; nt++) {
                    mma16816(acc[mt][nt*2],   aH[mt], &bH[nt][0]);
                    mma16816(acc[mt][nt*2+1], aH[mt], &bH[nt][2]);
                }
#pragma unroll
            for (int mt = 0; mt < 2; mt++)
#pragma unroll
                for (int nt = 0; nt < 2; nt++) {
                    mma16816(acc[mt][nt*2],   aH[mt], &bL[nt][0]);
                    mma16816(acc[mt][nt*2+1], aH[mt], &bL[nt][2]);
                }
#pragma unroll
            for (int mt = 0; mt < 2; mt++)
#pragma unroll
                for (int nt = 0; nt < 2; nt++) {
                    mma16816(acc[mt][nt*2],   aL[mt], &bH[nt][0]);
                    mma16816(acc[mt][nt*2+1], aL[mt], &bH[nt][2]);
                }
        }
        if (kc + 2 < S) load_stage((kc + 2) % 3, kc + 2);
    }
    __syncthreads();

    // ---- epilogue: d -> smem, VN-ReLU across the 3 v planes, write Y h/l ----
    float* sC = (float*)dsm;   // [96 rows(v*32+nn)][132 pad]
    int gid = lane >> 2, q = lane & 3;
#pragma unroll
    for (int mt = 0; mt < 2; mt++)
#pragma unroll
        for (int j = 0; j < 4; j++) {
            int ml = wm*32 + mt*16 + gid;
            int nl = wn*32 + j*8 + q*2;
            sC[nl*132 + ml]         = acc[mt][j][0];
            sC[(nl+1)*132 + ml]     = acc[mt][j][1];
            sC[nl*132 + ml + 8]     = acc[mt][j][2];
            sC[(nl+1)*132 + ml + 8] = acc[mt][j][3];
        }
    __syncthreads();

    int bv0 = bidx * 3;
#pragma unroll
    for (int it = 0; it < 3; it++) {
        int w = it * 384 + tid;      // 1024 items: nn(32) x chq(32)
        if (w >= 1024) break;
        int nn = w >> 5;
        int ch = (w & 31) << 2;
        int mych = m0 + ch;
        float d[3][4], x[3][4];
#pragma unroll
        for (int v = 0; v < 3; v++) {
            const float* sm = sC + (v*32 + nn) * 132 + ch;
            d[v][0] = sm[0]; d[v][1] = sm[1]; d[v][2] = sm[2]; d[v][3] = sm[3];
            if (bias) {
#pragma unroll
                for (int j = 0; j < 4; j++) d[v][j] += bias[(mych + j) * 12 + bv0 + v];
            }
            int col = colb + v * 2048 + nn;
            if (pool != nullptr && mych >= 128) {
#pragma unroll
                for (int j = 0; j < 4; j++)
                    x[v][j] = pool[(mych + j - 128) * 12 + bv0 + v] * INV_N;
            } else {
                size_t xo = (size_t)col * ldx + mych;
                __nv_bfloat162 h01 = *(const __nv_bfloat162*)(Xh + xo);
                __nv_bfloat162 h23 = *(const __nv_bfloat162*)(Xh + xo + 2);
                __nv_bfloat162 l01 = *(const __nv_bfloat162*)(Xl + xo);
                __nv_bfloat162 l23 = *(const __nv_bfloat162*)(Xl + xo + 2);
                x[v][0] = bfre(h01.x, l01.x); x[v][1] = bfre(h01.y, l01.y);
                x[v][2] = bfre(h23.x, l23.x); x[v][3] = bfre(h23.y, l23.y);
            }
        }
        float y[3][4];
#pragma unroll
        for (int j = 0; j < 4; j++) {
            float dot = x[0][j]*d[0][j] + x[1][j]*d[1][j] + x[2][j]*d[2][j];
            float dsq = d[0][j]*d[0][j] + d[1][j]*d[1][j] + d[2][j]*d[2][j] + 1e-8f;
            float tt = (dot >= 0.f) ? 0.f : dot / dsq;
            y[0][j] = x[0][j] - tt*d[0][j];
            y[1][j] = x[1][j] - tt*d[1][j];
            y[2][j] = x[2][j] - tt*d[2][j];
        }
#pragma unroll
        for (int v = 0; v < 3; v++) {
            size_t yo = (size_t)(colb + v * 2048 + nn) * ldy + mych;
            __nv_bfloat16 h0 = __float2bfloat16(y[v][0]), h1 = __float2bfloat16(y[v][1]);
            __nv_bfloat16 h2 = __float2bfloat16(y[v][2]), h3 = __float2bfloat16(y[v][3]);
            *(__nv_bfloat162*)(Yh + yo)     = __halves2bfloat162(h0, h1);
            *(__nv_bfloat162*)(Yh + yo + 2) = __halves2bfloat162(h2, h3);
            *(__nv_bfloat162*)(Yl + yo) = __halves2bfloat162(
                __float2bfloat16(y[v][0] - __bfloat162float(h0)),
                __float2bfloat16(y[v][1] - __bfloat162float(h1)));
            *(__nv_bfloat162*)(Yl + yo + 2) = __halves2bfloat162(
                __float2bfloat16(y[v][2] - __bfloat162float(h2)),
                __float2bfloat16(y[v][3] - __bfloat162float(h3)));
        }
    }
}

// ---------------- combined rank-12 projections (PD0 + PWS), 36 blocks x 128 ----------------
// pl holds UN-NORMALIZED pool sums; result scaled by 1/2048.
__global__ __launch_bounds__(128) void proj2(const float* __restrict__ d0w,
                                             const float* __restrict__ Wsw,
                                             const float* __restrict__ pl,
                                             float* __restrict__ PD0,
                                             float* __restrict__ PWS) {
    int idx = blockIdx.x * 128 + threadIdx.x;
    if (idx >= 4608) return;     // 384 * 12
    int o = idx / 12, bv = idx - o * 12;
    const float* Ar; float* outp; int oo = o;
    if (o < 256) { Ar = d0w + o * 256 + 128; outp = PD0; }
    else         { oo = o - 256; Ar = Wsw + oo * 256 + 128; outp = PWS; }
    float s = 0.f;
#pragma unroll 4
    for (int c = 0; c < 128; c++) s += Ar[c] * pl[c * 12 + bv];
    outp[oo * 12 + bv] = s * INV_N;
}

// ---------------- final head (reads un-normalized pool sums) ----------------
__global__ __launch_bounds__(512) void final_head(const float* __restrict__ PS,
                                                  const float* __restrict__ act_d,
                                                  const float* __restrict__ fc_c,
                                                  float* __restrict__ out) {
    __shared__ float spf[1536], sd[1536], sy[1536];
    int tid = threadIdx.x;
    for (int i = tid; i < 1536; i += 512) spf[i] = PS[i] * INV_N;
    __syncthreads();
    for (int i = tid; i < 1536; i += 512) {
        int o = i / 12, bv = i - o * 12;
        float s = 0.f;
        for (int c = 0; c < 128; c++) s += act_d[o*128 + c] * spf[c*12 + bv];
        sd[i] = s;
    }
    __syncthreads();
    {
        int o = tid >> 2, b = tid & 3;
        int base = o * 12 + b * 3;
        float x0 = spf[base], x1 = spf[base+1], x2 = spf[base+2];
        float d0 = sd[base],  d1 = sd[base+1],  d2 = sd[base+2];
        float dot = x0*d0 + x1*d1 + x2*d2;
        float dsq = d0*d0 + d1*d1 + d2*d2 + 1e-8f;
        float t = (dot >= 0.f) ? 0.f : dot / dsq;
        sy[base]   = x0 - t*d0;
        sy[base+1] = x1 - t*d1;
        sy[base+2] = x2 - t*d2;
    }
    __syncthreads();
    for (int i = tid; i < 1536; i += 512) {
        int o = i / 12, bv = i - o * 12;
        int b = bv / 3, v = bv - b * 3;
        float s = 0.f;
        for (int c = 0; c < 128; c++) s += fc_c[o*128 + c] * sy[c*12 + bv];
        out[b * 384 + o * 3 + v] = s;
    }
}

// ---------------- launcher ----------------
extern "C" void kernel_launch(void* const* d_in, const int* in_sizes, int n_in,
                              void* d_out, int out_size) {
    const float* p        = (const float*)d_in[0];
    const float* fc_pos_W = (const float*)d_in[1];
    const float* blk_d0   = (const float*)d_in[2];
    const float* blk_W0   = (const float*)d_in[3];
    const float* blk_d1   = (const float*)d_in[4];
    const float* blk_W1   = (const float*)d_in[5];
    const float* blk_Ws   = (const float*)d_in[6];
    const float* fc_c_W   = (const float*)d_in[7];
    const float* act_d    = (const float*)d_in[8];
    float* out = (float*)d_out;

    const size_t SMM = 86016;   // 3 x 28672
    cudaFuncSetAttribute(hgemm,  cudaFuncAttributeMaxDynamicSharedMemorySize, SMM);
    cudaFuncSetAttribute(hgemmF, cudaFuncAttributeMaxDynamicSharedMemorySize, SMM);
    cudaFuncSetAttribute(knn_mean4, cudaFuncAttributeMaxDynamicSharedMemorySize, 57344);

    float *MEAN, *POOLSUM, *PD0, *PWS;
    __nv_bfloat16 *XIN0h, *XIN0l, *Yh, *Yl, *Hh, *Hl, *Y2h, *Y2l, *N0h, *N0l, *N1h, *N1l, *Wh, *Wl;
    cudaGetSymbolAddress((void**)&MEAN, g_mean);
    cudaGetSymbolAddress((void**)&POOLSUM, g_poolsum);
    cudaGetSymbolAddress((void**)&PD0, g_Pd0);
    cudaGetSymbolAddress((void**)&PWS, g_PWs);
    cudaGetSymbolAddress((void**)&XIN0h, g_XIN0h);
    cudaGetSymbolAddress((void**)&XIN0l, g_XIN0l);
    cudaGetSymbolAddress((void**)&Yh, g_Yh);
    cudaGetSymbolAddress((void**)&Yl, g_Yl);
    cudaGetSymbolAddress((void**)&Hh, g_Hh);
    cudaGetSymbolAddress((void**)&Hl, g_Hl);
    cudaGetSymbolAddress((void**)&Y2h, g_Y2h);
    cudaGetSymbolAddress((void**)&Y2l, g_Y2l);
    cudaGetSymbolAddress((void**)&N0h, g_N0h);
    cudaGetSymbolAddress((void**)&N0l, g_N0l);
    cudaGetSymbolAddress((void**)&N1h, g_N1h);
    cudaGetSymbolAddress((void**)&N1l, g_N1l);
    cudaGetSymbolAddress((void**)&Wh, g_Wh);
    cudaGetSymbolAddress((void**)&Wl, g_Wl);

    splitall<<<2944, 256>>>(blk_d0, blk_W0, blk_d1, blk_W1, blk_Ws, Wh, Wl);
    knn_mean4<<<2048, 256, 57344>>>(p, MEAN);
    feat_t<<<NCOLS / 8, 256>>>(p, MEAN, fc_pos_W, XIN0h, XIN0l);

    const dim3 GF1(256, 1), GF2(256, 2), G1(256, 1);

    // ---- block 0 ----
    hgemmF<<<GF2, 384, SMM>>>(Wh+OFF_D0, Wl+OFF_D0, 256, 256,
                              XIN0h, XIN0l, 256, XIN0h, XIN0l, 256, nullptr,
                              Yh, Yl, 256, nullptr);
    hgemm<<<G1, 384, SMM>>>(Wh+OFF_W0, Wl+OFF_W0, 256, 256, 256,
                            Yh, Yl, 256, Yh, Yl, 256, Hh, Hl, 128, nullptr, nullptr);
    hgemmF<<<GF1, 384, SMM>>>(Wh+OFF_D1, Wl+OFF_D1, 128, 128,
                              Hh, Hl, 128, Hh, Hl, 128, nullptr,
                              Y2h, Y2l, 128, nullptr);
    cudaMemsetAsync(POOLSUM, 0, 1536 * sizeof(float));
    hgemm<<<G1, 384, SMM>>>(Wh+OFF_SW0, Wl+OFF_SW0, 384, 384, 256,
                            XIN0h, XIN0l, 256, Y2h, Y2l, 128, N1h, N1l, 128, nullptr, POOLSUM);

    // ---- blocks 1..4 ----
    __nv_bfloat16 *NINh = N1h, *NINl = N1l, *NOh = N0h, *NOl = N0l;
    for (int i = 1; i < 5; i++) {
        int swoff = OFF_SWI + (i - 1) * 32768;
        proj2<<<36, 128>>>(blk_d0 + i * 65536, blk_Ws + i * 32768, POOLSUM, PD0, PWS);

        hgemmF<<<GF2, 384, SMM>>>(Wh+OFF_D0+i*65536, Wl+OFF_D0+i*65536, 256, 128,
                                  NINh, NINl, 128, NINh, NINl, 128, POOLSUM,
                                  Yh, Yl, 256, PD0);
        hgemm<<<G1, 384, SMM>>>(Wh+OFF_W0+i*32768, Wl+OFF_W0+i*32768, 256, 256, 256,
                                Yh, Yl, 256, Yh, Yl, 256, Hh, Hl, 128, nullptr, nullptr);
        hgemmF<<<GF1, 384, SMM>>>(Wh+OFF_D1+i*16384, Wl+OFF_D1+i*16384, 128, 128,
                                  Hh, Hl, 128, Hh, Hl, 128, nullptr,
                                  Y2h, Y2l, 128, nullptr);
        cudaMemsetAsync(POOLSUM, 0, 1536 * sizeof(float));
        hgemm<<<G1, 384, SMM>>>(Wh+swoff, Wl+swoff, 256, 256, 128,
                                NINh, NINl, 128, Y2h, Y2l, 128, NOh, NOl, 128, PWS, POOLSUM);

        __nv_bfloat16* tb;
        tb = NINh; NINh = NOh; NOh = tb;
        tb = NINl; NINl = NOl; NOl = tb;
    }

    // ---- final head (POOLSUM accumulated by block-4 SW gemm) ----
    final_head<<<1, 512>>>(POOLSUM, act_d, fc_c_W, out);
}

// round 17
// speedup vs baseline: 1.0338x; 1.0122x over previous
#include <cuda_runtime.h>
#include <cuda_bf16.h>
#include <cstdint>

#define NCOLS 24576   // B*3*N = 4*3*2048
#define NPTS  2048
#define BATCH 4
#define KNN   20

// ---------------- static scratch (bf16 hi/lo activations, [col][channel]) ----------------
__device__ __nv_bfloat16 g_XIN0h[6291456], g_XIN0l[6291456];   // [24576][256]
__device__ __nv_bfloat16 g_Yh[6291456],   g_Yl[6291456];       // [24576][256]
__device__ __nv_bfloat16 g_Hh[3145728],   g_Hl[3145728];       // [24576][128]
__device__ __nv_bfloat16 g_Y2h[3145728],  g_Y2l[3145728];
__device__ __nv_bfloat16 g_N0h[3145728],  g_N0l[3145728];
__device__ __nv_bfloat16 g_N1h[3145728],  g_N1l[3145728];
__device__ __nv_bfloat16 g_Wh[819200],    g_Wl[819200];
__device__ float g_mean[BATCH * NPTS * 3];
__device__ float g_poolsum[5 * 1536];     // per-block un-normalized column sums (x2048)
__device__ float g_Pd0[256 * 12];
__device__ float g_PWs[128 * 12];

// weight regions inside g_Wh/g_Wl
#define OFF_D0  0         // 5 x 256x256
#define OFF_W0  327680    // 5 x 128x256
#define OFF_D1  491520    // 5 x 128x128
#define OFF_SW0 573440    // block0 [Ws|W1] 128x384
#define OFF_SWI 622592    // blocks1-4 [Ws[:, :128]|W1] 128x256 each

#define INV_N (1.f / 2048.f)

// ---------------- ptx helpers ----------------
__device__ __forceinline__ void cpa16(uint32_t dst, const void* src) {
    asm volatile("cp.async.cg.shared.global [%0], [%1], 16;\n" :: "r"(dst), "l"(src));
}
__device__ __forceinline__ void ldsm4(uint32_t* r, uint32_t addr) {
    asm volatile("ldmatrix.sync.aligned.m8n8.x4.shared.b16 {%0,%1,%2,%3}, [%4];"
                 : "=r"(r[0]), "=r"(r[1]), "=r"(r[2]), "=r"(r[3]) : "r"(addr));
}
__device__ __forceinline__ void mma16816(float* c, const uint32_t* a, const uint32_t* b) {
    asm volatile("mma.sync.aligned.m16n8k16.row.col.f32.bf16.bf16.f32 "
                 "{%0,%1,%2,%3}, {%4,%5,%6,%7}, {%8,%9}, {%0,%1,%2,%3};"
                 : "+f"(c[0]), "+f"(c[1]), "+f"(c[2]), "+f"(c[3])
                 : "r"(a[0]), "r"(a[1]), "r"(a[2]), "r"(a[3]), "r"(b[0]), "r"(b[1]));
}
__device__ __forceinline__ float bfre(__nv_bfloat16 h, __nv_bfloat16 l) {
    return __bfloat162float(h) + __bfloat162float(l);
}

// SW128 swizzle: bits[6:4] ^= bits[9:7] (conflict-free ldsm on 128B rows)
#define SWZ128(x) ((x) ^ (((x) >> 3) & 0x70))

// stage: A[128 rows][128B: hi 64 | lo 64] 16384B, then B[96 rows][128B] 12288B
#define FSTG 28672u
#define BOFS 16384u

// ---------------- all weight splits + POOLSUM zeroing in ONE launch ----------------
__global__ __launch_bounds__(256) void splitall(const float* __restrict__ d0,
                                                const float* __restrict__ W0,
                                                const float* __restrict__ d1,
                                                const float* __restrict__ W1,
                                                const float* __restrict__ Ws,
                                                __nv_bfloat16* __restrict__ Wh,
                                                __nv_bfloat16* __restrict__ Wl,
                                                float* __restrict__ poolsum) {
    int i = blockIdx.x * 256 + threadIdx.x;
    float x; int di;
    if (i < 327680) { x = d0[i]; di = OFF_D0 + i; }
    else if (i < 491520) { int j = i - 327680; x = W0[j]; di = OFF_W0 + j; }
    else if (i < 573440) { int j = i - 491520; x = d1[j]; di = OFF_D1 + j; }
    else if (i < 622592) {
        int j = i - 573440; int m = j / 384, k = j - m * 384;
        x = (k < 256) ? Ws[m*256 + k] : W1[m*128 + (k - 256)];
        di = OFF_SW0 + j;
    } else if (i < 753664) {
        int j = i - 622592; int blk = j >> 15; int jj = j & 32767;
        int m = jj >> 8, k = jj & 255;
        x = (k < 128) ? Ws[(blk+1)*32768 + m*256 + k] : W1[(blk+1)*16384 + m*128 + (k-128)];
        di = OFF_SWI + j;
    } else {
        int j = i - 753664;
        if (j < 5 * 1536) poolsum[j] = 0.f;
        return;
    }
    __nv_bfloat16 h = __float2bfloat16(x);
    Wh[di] = h;
    Wl[di] = __float2bfloat16(x - __bfloat162float(h));
}

// ---------------- KNN mean: 4 queries per block, 2 warps per query ----------------
__global__ __launch_bounds__(256) void knn_mean4(const float* __restrict__ p,
                                                 float* __restrict__ outm) {
    extern __shared__ float sm[];
    float* sx = sm;              // 2048
    float* sy = sm + 2048;
    float* sz = sm + 4096;
    float* sd = sm + 6144;       // 4 x 2048
    __shared__ float swv[4][2];
    __shared__ int   swi[4][2];
    __shared__ float sacc[4][3];
    int blk = blockIdx.x;        // 0..2047
    int b = blk >> 9;            // 512 blocks per batch
    int q0 = (blk & 511) * 4;    // base query index within batch
    int tid = threadIdx.x;
    const float* pb = p + b * NPTS * 3;
    for (int i = tid; i < NPTS; i += 256) {
        sx[i] = pb[i*3+0]; sy[i] = pb[i*3+1]; sz[i] = pb[i*3+2];
    }
    if (tid < 4) { sacc[tid][0] = 0.f; sacc[tid][1] = 0.f; sacc[tid][2] = 0.f; }
    __syncthreads();
    float qx[4], qy[4], qz[4], qq[4];
#pragma unroll
    for (int qi = 0; qi < 4; qi++) {
        int n = q0 + qi;
        qx[qi] = sx[n]; qy[qi] = sy[n]; qz[qi] = sz[n];
        qq[qi] = qx[qi]*qx[qi] + qy[qi]*qy[qi] + qz[qi]*qz[qi];
    }
    for (int i = tid; i < NPTS; i += 256) {
        float x = sx[i], y = sy[i], z = sz[i];
        float xx = x*x + y*y + z*z;
#pragma unroll
        for (int qi = 0; qi < 4; qi++)
            sd[qi*2048 + i] = 2.f*(qx[qi]*x + qy[qi]*y + qz[qi]*z) - qq[qi] - xx;
    }
    __syncthreads();
    int w = tid >> 5, lane = tid & 31;
    int myq = w >> 1, half = w & 1;
    float* sdq = sd + myq * 2048;
    for (int r = 0; r < KNN; r++) {
        float bv = -3.4e38f; int bi = 1 << 30;
#pragma unroll 4
        for (int j = 0; j < 32; j++) {
            int i = half*1024 + j*32 + lane;
            float v = sdq[i];
            if (v > bv) { bv = v; bi = i; }        // ascending i -> smallest idx wins ties
        }
        for (int off = 16; off; off >>= 1) {
            float ov = __shfl_down_sync(0xffffffffu, bv, off);
            int   oi = __shfl_down_sync(0xffffffffu, bi, off);
            if (ov > bv || (ov == bv && oi < bi)) { bv = ov; bi = oi; }
        }
        if (lane == 0) { swv[myq][half] = bv; swi[myq][half] = bi; }
        __syncthreads();
        if (lane == 0 && half == 0) {
            float v0 = swv[myq][0], v1 = swv[myq][1];
            int   i0 = swi[myq][0], i1 = swi[myq][1];
            int bj = (v0 > v1 || (v0 == v1 && i0 < i1)) ? i0 : i1;
            sacc[myq][0] += sx[bj];
            sacc[myq][1] += sy[bj];
            sacc[myq][2] += sz[bj];
            sdq[bj] = -3.4e38f;
        }
        __syncthreads();
    }
    if (tid < 4) {
        int gid = b * NPTS + q0 + tid;
        const float inv = 1.f / KNN;
        outm[gid*3+0] = sacc[tid][0] * inv;
        outm[gid*3+1] = sacc[tid][1] * inv;
        outm[gid*3+2] = sacc[tid][2] * inv;
    }
}

// ------------- feat: out[col][256] bf16 hi/lo -------------
__global__ __launch_bounds__(256) void feat_t(const float* __restrict__ p,
                                              const float* __restrict__ m,
                                              const float* __restrict__ W,
                                              __nv_bfloat16* __restrict__ Xh,
                                              __nv_bfloat16* __restrict__ Xl) {
    __shared__ float sW[768];
    int tid = threadIdx.x;
    for (int i = tid; i < 768; i += 256) sW[i] = W[i];
    __syncthreads();
    int wid = tid >> 5, lane = tid & 31;
    int col = blockIdx.x * 8 + wid;
    int b = col / 6144;
    int rem = col - b * 6144;
    int v = rem >> 11;
    int n = rem & 2047;
    int pi = (b * NPTS + n) * 3;
    float px = p[pi], py = p[pi+1], pz = p[pi+2];
    float mx = m[pi], my = m[pi+1], mz = m[pi+2];
    float pv, mv, cv;
    if (v == 0)      { pv = px; mv = mx; cv = my*pz - mz*py; }
    else if (v == 1) { pv = py; mv = my; cv = mz*px - mx*pz; }
    else             { pv = pz; mv = mz; cv = mx*py - my*px; }
#pragma unroll
    for (int j = 0; j < 8; j++) {
        int o = j * 32 + lane;
        float r = sW[o*3]*(mv - pv) + sW[o*3+1]*pv + sW[o*3+2]*cv;
        size_t idx = (size_t)col * 256 + o;
        __nv_bfloat16 h = __float2bfloat16(r);
        Xh[idx] = h;
        Xl[idx] = __float2bfloat16(r - __bfloat162float(h));
    }
}

// ---------------- plain split-bf16 HMMA GEMM, 384 threads, swizzled smem ----------------
// BM=128, BN=96, BK=32; warp tile 32x32; 3-stage pipeline; SW128 conflict-free layout.
// Optional poolAcc: accumulates un-normalized column sums (after bias).
// If Ch == nullptr, the bf16 output stores are skipped (pool-only epilogue).
__global__ __launch_bounds__(384, 2)
void hgemm(const __nv_bfloat16* __restrict__ Ah, const __nv_bfloat16* __restrict__ Al,
           int lda, int K, int Ksplit,
           const __nv_bfloat16* __restrict__ B1h, const __nv_bfloat16* __restrict__ B1l, int ldb1,
           const __nv_bfloat16* __restrict__ B2h, const __nv_bfloat16* __restrict__ B2l, int ldb2,
           __nv_bfloat16* __restrict__ Ch, __nv_bfloat16* __restrict__ Cl, int ldc,
           const float* __restrict__ bias,
           float* __restrict__ poolAcc)
{
    extern __shared__ __align__(16) unsigned char dsm[];
    uint32_t smB = (uint32_t)__cvta_generic_to_shared(dsm);
    int tid = threadIdx.x, lane = tid & 31, wid = tid >> 5;
    int wm = wid & 3, wn = wid >> 2;          // wm 0..3, wn 0..2
    int col0 = blockIdx.x * 96, m0 = blockIdx.y * 128;

    float acc[2][4][4];
#pragma unroll
    for (int a = 0; a < 2; a++)
#pragma unroll
        for (int b = 0; b < 4; b++)
#pragma unroll
            for (int c = 0; c < 4; c++) acc[a][b][c] = 0.f;

    int S = K >> 5;

    auto load_stage = [&](int s, int kc) {
        uint32_t SB = smB + (uint32_t)s * FSTG;
        int kk = kc << 5;
#pragma unroll
        for (int part = 0; part < 3; part++) {
            int j = tid + part * 384;
            if (j < 1024) {
                int r = j >> 3, c = j & 7;
                const __nv_bfloat16* src = (c < 4) ? Ah : Al;
                uint32_t sw = SWZ128((uint32_t)(r * 128 + c * 16));
                cpa16(SB + sw, src + (size_t)(m0 + r) * lda + kk + (c & 3) * 8);
            }
        }
        {
            const __nv_bfloat16 *bh, *bl; int kb, ldb;
            if (kk < Ksplit) { bh = B1h; bl = B1l; kb = kk; ldb = ldb1; }
            else             { bh = B2h; bl = B2l; kb = kk - Ksplit; ldb = ldb2; }
#pragma unroll
            for (int part = 0; part < 2; part++) {
                int j = tid + part * 384;
                if (j < 768) {
                    int r = j >> 3, c = j & 7;
                    const __nv_bfloat16* src = (c < 4) ? bh : bl;
                    uint32_t sw = SWZ128((uint32_t)(r * 128 + c * 16));
                    cpa16(SB + BOFS + sw, src + (size_t)(col0 + r) * ldb + kb + (c & 3) * 8);
                }
            }
        }
        asm volatile("cp.async.commit_group;\n" ::);
    };

    load_stage(0, 0);
    load_stage(1, 1);
    for (int kc = 0; kc < S; kc++) {
        int s = kc % 3;
        if (kc + 1 < S) { asm volatile("cp.async.wait_group 1;\n" ::); }
        else            { asm volatile("cp.async.wait_group 0;\n" ::); }
        __syncthreads();
        uint32_t SB = smB + (uint32_t)s * FSTG;
#pragma unroll
        for (int kt = 0; kt < 2; kt++) {
            uint32_t aH[2][4], aL[2][4], bH[2][4], bL[2][4];
#pragma unroll
            for (int mt = 0; mt < 2; mt++) {
                uint32_t row = (uint32_t)(wm*32 + mt*16 + (lane & 15));
                uint32_t ch = (uint32_t)(kt*2) + (uint32_t)(lane >> 4);
                ldsm4(aH[mt], SB + SWZ128(row*128u + ch*16u));
                ldsm4(aL[mt], SB + SWZ128(row*128u + (ch+4u)*16u));
            }
#pragma unroll
            for (int nt = 0; nt < 2; nt++) {
                uint32_t row = (uint32_t)(wn*32 + nt*16 + ((lane >> 4) << 3) + (lane & 7));
                uint32_t ch = (uint32_t)(kt*2) + ((uint32_t)(lane >> 3) & 1u);
                ldsm4(bH[nt], SB + BOFS + SWZ128(row*128u + ch*16u));
                ldsm4(bL[nt], SB + BOFS + SWZ128(row*128u + (ch+4u)*16u));
            }
#pragma unroll
            for (int mt = 0; mt < 2; mt++)
#pragma unroll
                for (int nt = 0; nt < 2; nt++) {
                    mma16816(acc[mt][nt*2],   aH[mt], &bH[nt][0]);
                    mma16816(acc[mt][nt*2+1], aH[mt], &bH[nt][2]);
                }
#pragma unroll
            for (int mt = 0; mt < 2; mt++)
#pragma unroll
                for (int nt = 0; nt < 2; nt++) {
                    mma16816(acc[mt][nt*2],   aH[mt], &bL[nt][0]);
                    mma16816(acc[mt][nt*2+1], aH[mt], &bL[nt][2]);
                }
#pragma unroll
            for (int mt = 0; mt < 2; mt++)
#pragma unroll
                for (int nt = 0; nt < 2; nt++) {
                    mma16816(acc[mt][nt*2],   aL[mt], &bH[nt][0]);
                    mma16816(acc[mt][nt*2+1], aL[mt], &bH[nt][2]);
                }
        }
        if (kc + 2 < S) load_stage((kc + 2) % 3, kc + 2);
    }
    __syncthreads();

    // ---- epilogue: regs -> smem transpose -> coalesced h/l stores (+ optional pool acc) ----
    float* sC = (float*)dsm;       // [96 cols][132 pad]
    int gid = lane >> 2, q = lane & 3;
#pragma unroll
    for (int mt = 0; mt < 2; mt++)
#pragma unroll
        for (int j = 0; j < 4; j++) {
            int ml = wm*32 + mt*16 + gid;
            int nl = wn*32 + j*8 + q*2;
            sC[nl*132 + ml]         = acc[mt][j][0];
            sC[(nl+1)*132 + ml]     = acc[mt][j][1];
            sC[nl*132 + ml + 8]     = acc[mt][j][2];
            sC[(nl+1)*132 + ml + 8] = acc[mt][j][3];
        }
    __syncthreads();
    int bvA = col0 >> 11;
    int bvLast = (col0 + 95) >> 11;
    bool cross = (bvLast != bvA);
    float ps0[4] = {0.f, 0.f, 0.f, 0.f};
    float ps1[4] = {0.f, 0.f, 0.f, 0.f};
#pragma unroll
    for (int it = 0; it < 8; it++) {
        int w = it * 384 + tid;      // 3072 items: c(96) x chq(32); ch fixed per thread
        int c = w >> 5;
        int ch = (w & 31) << 2;
        int col = col0 + c;
        int bv = col >> 11;
        size_t ob = (size_t)col * ldc + m0 + ch;
        const float* sm = sC + c * 132 + ch;
        float4 vq = *(const float4*)sm;
        if (bias) {
            vq.x += bias[(m0 + ch + 0) * 12 + bv];
            vq.y += bias[(m0 + ch + 1) * 12 + bv];
            vq.z += bias[(m0 + ch + 2) * 12 + bv];
            vq.w += bias[(m0 + ch + 3) * 12 + bv];
        }
        if (poolAcc) {
            float* pt = (bv == bvA) ? ps0 : ps1;
            pt[0] += vq.x; pt[1] += vq.y; pt[2] += vq.z; pt[3] += vq.w;
        }
        if (Ch) {
            __nv_bfloat16 h0 = __float2bfloat16(vq.x), h1 = __float2bfloat16(vq.y);
            __nv_bfloat16 h2 = __float2bfloat16(vq.z), h3 = __float2bfloat16(vq.w);
            *(__nv_bfloat162*)(Ch + ob)     = __halves2bfloat162(h0, h1);
            *(__nv_bfloat162*)(Ch + ob + 2) = __halves2bfloat162(h2, h3);
            *(__nv_bfloat162*)(Cl + ob) = __halves2bfloat162(
                __float2bfloat16(vq.x - __bfloat162float(h0)),
                __float2bfloat16(vq.y - __bfloat162float(h1)));
            *(__nv_bfloat162*)(Cl + ob + 2) = __halves2bfloat162(
                __float2bfloat16(vq.z - __bfloat162float(h2)),
                __float2bfloat16(vq.w - __bfloat162float(h3)));
        }
    }
    if (poolAcc) {
        float* sP = sC + 96 * 132;   // 256 floats of scratch
        __syncthreads();
        for (int i = tid; i < 256; i += 384) sP[i] = 0.f;
        __syncthreads();
        int ch = (tid & 31) << 2;
#pragma unroll
        for (int j = 0; j < 4; j++) atomicAdd(&sP[ch + j], ps0[j]);
        if (cross) {
#pragma unroll
            for (int j = 0; j < 4; j++) atomicAdd(&sP[128 + ch + j], ps1[j]);
        }
        __syncthreads();
        if (tid < 128) {
            atomicAdd(&poolAcc[tid * 12 + bvA], sP[tid]);
            if (cross) atomicAdd(&poolAcc[tid * 12 + bvLast], sP[128 + tid]);
        }
    }
}

// ---------------- FUSED D-GEMM + VN-ReLU, 384 threads, swizzled smem ----------------
// Column tile = 32 n-values x 3 vector comps (96 cols), warp tile 32x32.
// pool (if non-null) holds UN-NORMALIZED sums; scaled by 1/2048 at read.
__global__ __launch_bounds__(384, 2)
void hgemmF(const __nv_bfloat16* __restrict__ Ah, const __nv_bfloat16* __restrict__ Al,
            int lda, int K,
            const __nv_bfloat16* __restrict__ Bh, const __nv_bfloat16* __restrict__ Bl, int ldb,
            const __nv_bfloat16* __restrict__ Xh, const __nv_bfloat16* __restrict__ Xl, int ldx,
            const float* __restrict__ pool,
            __nv_bfloat16* __restrict__ Yh, __nv_bfloat16* __restrict__ Yl, int ldy,
            const float* __restrict__ bias)
{
    extern __shared__ __align__(16) unsigned char dsm[];
    uint32_t smB = (uint32_t)__cvta_generic_to_shared(dsm);
    int tid = threadIdx.x, lane = tid & 31, wid = tid >> 5;
    int wm = wid & 3, wn = wid >> 2;
    int t = blockIdx.x;
    int bidx = t >> 6;
    int n0 = (t & 63) * 32;
    int m0 = blockIdx.y * 128;
    int colb = bidx * 6144 + n0;

    float acc[2][4][4];
#pragma unroll
    for (int a = 0; a < 2; a++)
#pragma unroll
        for (int b = 0; b < 4; b++)
#pragma unroll
            for (int c = 0; c < 4; c++) acc[a][b][c] = 0.f;

    int S = K >> 5;

    auto load_stage = [&](int s, int kc) {
        uint32_t SB = smB + (uint32_t)s * FSTG;
        int kk = kc << 5;
#pragma unroll
        for (int part = 0; part < 3; part++) {
            int j = tid + part * 384;
            if (j < 1024) {
                int r = j >> 3, c = j & 7;
                const __nv_bfloat16* src = (c < 4) ? Ah : Al;
                uint32_t sw = SWZ128((uint32_t)(r * 128 + c * 16));
                cpa16(SB + sw, src + (size_t)(m0 + r) * lda + kk + (c & 3) * 8);
            }
        }
#pragma unroll
        for (int part = 0; part < 2; part++) {
            int j = tid + part * 384;
            if (j < 768) {
                int r = j >> 3, c = j & 7;
                const __nv_bfloat16* src = (c < 4) ? Bh : Bl;
                int col = colb + ((r >> 5) << 11) + (r & 31);
                uint32_t sw = SWZ128((uint32_t)(r * 128 + c * 16));
                cpa16(SB + BOFS + sw, src + (size_t)col * ldb + kk + (c & 3) * 8);
            }
        }
        asm volatile("cp.async.commit_group;\n" ::);
    };

    load_stage(0, 0);
    load_stage(1, 1);
    for (int kc = 0; kc < S; kc++) {
        int s = kc % 3;
        if (kc + 1 < S) { asm volatile("cp.async.wait_group 1;\n" ::); }
        else            { asm volatile("cp.async.wait_group 0;\n" ::); }
        __syncthreads();
        uint32_t SB = smB + (uint32_t)s * FSTG;
#pragma unroll
        for (int kt = 0; kt < 2; kt++) {
            uint32_t aH[2][4], aL[2][4], bH[2][4], bL[2][4];
#pragma unroll
            for (int mt = 0; mt < 2; mt++) {
                uint32_t row = (uint32_t)(wm*32 + mt*16 + (lane & 15));
                uint32_t ch = (uint32_t)(kt*2) + (uint32_t)(lane >> 4);
                ldsm4(aH[mt], SB + SWZ128(row*128u + ch*16u));
                ldsm4(aL[mt], SB + SWZ128(row*128u + (ch+4u)*16u));
            }
#pragma unroll
            for (int nt = 0; nt < 2; nt++) {
                uint32_t row = (uint32_t)(wn*32 + nt*16 + ((lane >> 4) << 3) + (lane & 7));
                uint32_t ch = (uint32_t)(kt*2) + ((uint32_t)(lane >> 3) & 1u);
                ldsm4(bH[nt], SB + BOFS + SWZ128(row*128u + ch*16u));
                ldsm4(bL[nt], SB + BOFS + SWZ128(row*128u + (ch+4u)*16u));
            }
#pragma unroll
            for (int mt = 0; mt < 2; mt++)
#pragma unroll
                for (int nt = 0; nt < 2; nt++) {
                    mma16816(acc[mt][nt*2],   aH[mt], &bH[nt][0]);
                    mma16816(acc[mt][nt*2+1], aH[mt], &bH[nt][2]);
                }
#pragma unroll
            for (int mt = 0; mt < 2; mt++)
#pragma unroll
                for (int nt = 0; nt < 2; nt++) {
                    mma16816(acc[mt][nt*2],   aH[mt], &bL[nt][0]);
                    mma16816(acc[mt][nt*2+1], aH[mt], &bL[nt][2]);
                }
#pragma unroll
            for (int mt = 0; mt < 2; mt++)
#pragma unroll
                for (int nt = 0; nt < 2; nt++) {
                    mma16816(acc[mt][nt*2],   aL[mt], &bH[nt][0]);
                    mma16816(acc[mt][nt*2+1], aL[mt], &bH[nt][2]);
                }
        }
        if (kc + 2 < S) load_stage((kc + 2) % 3, kc + 2);
    }
    __syncthreads();

    // ---- epilogue: d -> smem, VN-ReLU across the 3 v planes, write Y h/l ----
    float* sC = (float*)dsm;   // [96 rows(v*32+nn)][132 pad]
    int gid = lane >> 2, q = lane & 3;
#pragma unroll
    for (int mt = 0; mt < 2; mt++)
#pragma unroll
        for (int j = 0; j < 4; j++) {
            int ml = wm*32 + mt*16 + gid;
            int nl = wn*32 + j*8 + q*2;
            sC[nl*132 + ml]         = acc[mt][j][0];
            sC[(nl+1)*132 + ml]     = acc[mt][j][1];
            sC[nl*132 + ml + 8]     = acc[mt][j][2];
            sC[(nl+1)*132 + ml + 8] = acc[mt][j][3];
        }
    __syncthreads();

    int bv0 = bidx * 3;
#pragma unroll
    for (int it = 0; it < 3; it++) {
        int w = it * 384 + tid;      // 1024 items: nn(32) x chq(32)
        if (w >= 1024) break;
        int nn = w >> 5;
        int ch = (w & 31) << 2;
        int mych = m0 + ch;
        float d[3][4], x[3][4];
#pragma unroll
        for (int v = 0; v < 3; v++) {
            const float* sm = sC + (v*32 + nn) * 132 + ch;
            d[v][0] = sm[0]; d[v][1] = sm[1]; d[v][2] = sm[2]; d[v][3] = sm[3];
            if (bias) {
#pragma unroll
                for (int j = 0; j < 4; j++) d[v][j] += bias[(mych + j) * 12 + bv0 + v];
            }
            int col = colb + v * 2048 + nn;
            if (pool != nullptr && mych >= 128) {
#pragma unroll
                for (int j = 0; j < 4; j++)
                    x[v][j] = pool[(mych + j - 128) * 12 + bv0 + v] * INV_N;
            } else {
                size_t xo = (size_t)col * ldx + mych;
                __nv_bfloat162 h01 = *(const __nv_bfloat162*)(Xh + xo);
                __nv_bfloat162 h23 = *(const __nv_bfloat162*)(Xh + xo + 2);
                __nv_bfloat162 l01 = *(const __nv_bfloat162*)(Xl + xo);
                __nv_bfloat162 l23 = *(const __nv_bfloat162*)(Xl + xo + 2);
                x[v][0] = bfre(h01.x, l01.x); x[v][1] = bfre(h01.y, l01.y);
                x[v][2] = bfre(h23.x, l23.x); x[v][3] = bfre(h23.y, l23.y);
            }
        }
        float y[3][4];
#pragma unroll
        for (int j = 0; j < 4; j++) {
            float dot = x[0][j]*d[0][j] + x[1][j]*d[1][j] + x[2][j]*d[2][j];
            float dsq = d[0][j]*d[0][j] + d[1][j]*d[1][j] + d[2][j]*d[2][j] + 1e-8f;
            float tt = (dot >= 0.f) ? 0.f : dot / dsq;
            y[0][j] = x[0][j] - tt*d[0][j];
            y[1][j] = x[1][j] - tt*d[1][j];
            y[2][j] = x[2][j] - tt*d[2][j];
        }
#pragma unroll
        for (int v = 0; v < 3; v++) {
            size_t yo = (size_t)(colb + v * 2048 + nn) * ldy + mych;
            __nv_bfloat16 h0 = __float2bfloat16(y[v][0]), h1 = __float2bfloat16(y[v][1]);
            __nv_bfloat16 h2 = __float2bfloat16(y[v][2]), h3 = __float2bfloat16(y[v][3]);
            *(__nv_bfloat162*)(Yh + yo)     = __halves2bfloat162(h0, h1);
            *(__nv_bfloat162*)(Yh + yo + 2) = __halves2bfloat162(h2, h3);
            *(__nv_bfloat162*)(Yl + yo) = __halves2bfloat162(
                __float2bfloat16(y[v][0] - __bfloat162float(h0)),
                __float2bfloat16(y[v][1] - __bfloat162float(h1)));
            *(__nv_bfloat162*)(Yl + yo + 2) = __halves2bfloat162(
                __float2bfloat16(y[v][2] - __bfloat162float(h2)),
                __float2bfloat16(y[v][3] - __bfloat162float(h3)));
        }
    }
}

// ---------------- combined rank-12 projections (PD0 + PWS), 36 blocks x 128 ----------------
// pl holds UN-NORMALIZED pool sums; result scaled by 1/2048.
__global__ __launch_bounds__(128) void proj2(const float* __restrict__ d0w,
                                             const float* __restrict__ Wsw,
                                             const float* __restrict__ pl,
                                             float* __restrict__ PD0,
                                             float* __restrict__ PWS) {
    int idx = blockIdx.x * 128 + threadIdx.x;
    if (idx >= 4608) return;     // 384 * 12
    int o = idx / 12, bv = idx - o * 12;
    const float* Ar; float* outp; int oo = o;
    if (o < 256) { Ar = d0w + o * 256 + 128; outp = PD0; }
    else         { oo = o - 256; Ar = Wsw + oo * 256 + 128; outp = PWS; }
    float s = 0.f;
#pragma unroll 4
    for (int c = 0; c < 128; c++) s += Ar[c] * pl[c * 12 + bv];
    outp[oo * 12 + bv] = s * INV_N;
}

// ---------------- final head (reads un-normalized pool sums) ----------------
__global__ __launch_bounds__(512) void final_head(const float* __restrict__ PS,
                                                  const float* __restrict__ act_d,
                                                  const float* __restrict__ fc_c,
                                                  float* __restrict__ out) {
    __shared__ float spf[1536], sd[1536], sy[1536];
    int tid = threadIdx.x;
    for (int i = tid; i < 1536; i += 512) spf[i] = PS[i] * INV_N;
    __syncthreads();
    for (int i = tid; i < 1536; i += 512) {
        int o = i / 12, bv = i - o * 12;
        float s = 0.f;
        for (int c = 0; c < 128; c++) s += act_d[o*128 + c] * spf[c*12 + bv];
        sd[i] = s;
    }
    __syncthreads();
    {
        int o = tid >> 2, b = tid & 3;
        int base = o * 12 + b * 3;
        float x0 = spf[base], x1 = spf[base+1], x2 = spf[base+2];
        float d0 = sd[base],  d1 = sd[base+1],  d2 = sd[base+2];
        float dot = x0*d0 + x1*d1 + x2*d2;
        float dsq = d0*d0 + d1*d1 + d2*d2 + 1e-8f;
        float t = (dot >= 0.f) ? 0.f : dot / dsq;
        sy[base]   = x0 - t*d0;
        sy[base+1] = x1 - t*d1;
        sy[base+2] = x2 - t*d2;
    }
    __syncthreads();
    for (int i = tid; i < 1536; i += 512) {
        int o = i / 12, bv = i - o * 12;
        int b = bv / 3, v = bv - b * 3;
        float s = 0.f;
        for (int c = 0; c < 128; c++) s += fc_c[o*128 + c] * sy[c*12 + bv];
        out[b * 384 + o * 3 + v] = s;
    }
}

// ---------------- launcher ----------------
extern "C" void kernel_launch(void* const* d_in, const int* in_sizes, int n_in,
                              void* d_out, int out_size) {
    const float* p        = (const float*)d_in[0];
    const float* fc_pos_W = (const float*)d_in[1];
    const float* blk_d0   = (const float*)d_in[2];
    const float* blk_W0   = (const float*)d_in[3];
    const float* blk_d1   = (const float*)d_in[4];
    const float* blk_W1   = (const float*)d_in[5];
    const float* blk_Ws   = (const float*)d_in[6];
    const float* fc_c_W   = (const float*)d_in[7];
    const float* act_d    = (const float*)d_in[8];
    float* out = (float*)d_out;

    const size_t SMM = 86016;   // 3 x 28672
    cudaFuncSetAttribute(hgemm,  cudaFuncAttributeMaxDynamicSharedMemorySize, SMM);
    cudaFuncSetAttribute(hgemmF, cudaFuncAttributeMaxDynamicSharedMemorySize, SMM);
    cudaFuncSetAttribute(knn_mean4, cudaFuncAttributeMaxDynamicSharedMemorySize, 57344);

    float *MEAN, *POOLSUM, *PD0, *PWS;
    __nv_bfloat16 *XIN0h, *XIN0l, *Yh, *Yl, *Hh, *Hl, *Y2h, *Y2l, *N0h, *N0l, *N1h, *N1l, *Wh, *Wl;
    cudaGetSymbolAddress((void**)&MEAN, g_mean);
    cudaGetSymbolAddress((void**)&POOLSUM, g_poolsum);
    cudaGetSymbolAddress((void**)&PD0, g_Pd0);
    cudaGetSymbolAddress((void**)&PWS, g_PWs);
    cudaGetSymbolAddress((void**)&XIN0h, g_XIN0h);
    cudaGetSymbolAddress((void**)&XIN0l, g_XIN0l);
    cudaGetSymbolAddress((void**)&Yh, g_Yh);
    cudaGetSymbolAddress((void**)&Yl, g_Yl);
    cudaGetSymbolAddress((void**)&Hh, g_Hh);
    cudaGetSymbolAddress((void**)&Hl, g_Hl);
    cudaGetSymbolAddress((void**)&Y2h, g_Y2h);
    cudaGetSymbolAddress((void**)&Y2l, g_Y2l);
    cudaGetSymbolAddress((void**)&N0h, g_N0h);
    cudaGetSymbolAddress((void**)&N0l, g_N0l);
    cudaGetSymbolAddress((void**)&N1h, g_N1h);
    cudaGetSymbolAddress((void**)&N1l, g_N1l);
    cudaGetSymbolAddress((void**)&Wh, g_Wh);
    cudaGetSymbolAddress((void**)&Wl, g_Wl);

    // splits + zero all 5 POOLSUM slots: (753664 + 7680) / 256 = 2974 blocks
    splitall<<<2974, 256>>>(blk_d0, blk_W0, blk_d1, blk_W1, blk_Ws, Wh, Wl, POOLSUM);
    knn_mean4<<<2048, 256, 57344>>>(p, MEAN);
    feat_t<<<NCOLS / 8, 256>>>(p, MEAN, fc_pos_W, XIN0h, XIN0l);

    const dim3 GF1(256, 1), GF2(256, 2), G1(256, 1);

    // ---- block 0 ----
    hgemmF<<<GF2, 384, SMM>>>(Wh+OFF_D0, Wl+OFF_D0, 256, 256,
                              XIN0h, XIN0l, 256, XIN0h, XIN0l, 256, nullptr,
                              Yh, Yl, 256, nullptr);
    hgemm<<<G1, 384, SMM>>>(Wh+OFF_W0, Wl+OFF_W0, 256, 256, 256,
                            Yh, Yl, 256, Yh, Yl, 256, Hh, Hl, 128, nullptr, nullptr);
    hgemmF<<<GF1, 384, SMM>>>(Wh+OFF_D1, Wl+OFF_D1, 128, 128,
                              Hh, Hl, 128, Hh, Hl, 128, nullptr,
                              Y2h, Y2l, 128, nullptr);
    hgemm<<<G1, 384, SMM>>>(Wh+OFF_SW0, Wl+OFF_SW0, 384, 384, 256,
                            XIN0h, XIN0l, 256, Y2h, Y2l, 128, N1h, N1l, 128, nullptr,
                            POOLSUM);   // slot 0

    // ---- blocks 1..4 ----
    __nv_bfloat16 *NINh = N1h, *NINl = N1l, *NOh = N0h, *NOl = N0l;
    for (int i = 1; i < 5; i++) {
        int swoff = OFF_SWI + (i - 1) * 32768;
        float* PSprev = POOLSUM + (i - 1) * 1536;
        float* PScur  = POOLSUM + i * 1536;
        proj2<<<36, 128>>>(blk_d0 + i * 65536, blk_Ws + i * 32768, PSprev, PD0, PWS);

        hgemmF<<<GF2, 384, SMM>>>(Wh+OFF_D0+i*65536, Wl+OFF_D0+i*65536, 256, 128,
                                  NINh, NINl, 128, NINh, NINl, 128, PSprev,
                                  Yh, Yl, 256, PD0);
        hgemm<<<G1, 384, SMM>>>(Wh+OFF_W0+i*32768, Wl+OFF_W0+i*32768, 256, 256, 256,
                                Yh, Yl, 256, Yh, Yl, 256, Hh, Hl, 128, nullptr, nullptr);
        hgemmF<<<GF1, 384, SMM>>>(Wh+OFF_D1+i*16384, Wl+OFF_D1+i*16384, 128, 128,
                                  Hh, Hl, 128, Hh, Hl, 128, nullptr,
                                  Y2h, Y2l, 128, nullptr);
        if (i < 4) {
            hgemm<<<G1, 384, SMM>>>(Wh+swoff, Wl+swoff, 256, 256, 128,
                                    NINh, NINl, 128, Y2h, Y2l, 128, NOh, NOl, 128, PWS,
                                    PScur);
        } else {
            // block 4: NET is consumed only via POOLSUM -> skip the dead bf16 stores
            hgemm<<<G1, 384, SMM>>>(Wh+swoff, Wl+swoff, 256, 256, 128,
                                    NINh, NINl, 128, Y2h, Y2l, 128, nullptr, nullptr, 128, PWS,
                                    PScur);
        }

        __nv_bfloat16* tb;
        tb = NINh; NINh = NOh; NOh = tb;
        tb = NINl; NINl = NOl; NOl = tb;
    }

    // ---- final head (POOLSUM slot 4) ----
    final_head<<<1, 512>>>(POOLSUM + 4 * 1536, act_d, fc_c_W, out);
}